// round 11
// baseline (speedup 1.0000x reference)
#include <cuda_runtime.h>
#include <cuda_fp16.h>
#include <math.h>
#include <stdint.h>

// ---------------------------------------------------------------------------
// TaskAwareMoE round 11: fp16 mma.sync grouped GEMMs with pre-packed fp16x2
// operands, prep folded into 6 total kernel launches (prep/gate/scan/place/
// ffn1/ffn2). Arithmetic bit-identical to round 9.
// ---------------------------------------------------------------------------

#define D_MODEL   512
#define D_FF      2048
#define N_EXPERTS 8
#define BATCH     8
#define SEQ       1024
#define TOK       (BATCH * SEQ)            // 8192
#define EXP_ROWS  (2 * TOK)                // 16384
#define TOT_ROWS  (EXP_ROWS + TOK)         // 24576
#define OUT_ELEMS (TOK * D_MODEL)          // 4,194,304
#define NGRP      (N_EXPERTS + 1)
#define XKP       (D_MODEL / 2)            // 256 k-pairs per X row
#define HKP       (D_FF / 2)               // 1024 k-pairs per H row

#define ASTRIDE 12      // uint32 words per A row  (8 used + 4 pad) -> bank-free
#define BSTRIDE 136     // uint32 words per B k-pair row (128 used + 8 pad)

// ----------------------------- static scratch ------------------------------
__device__ uint32_t g_Hh[(size_t)TOT_ROWS * HKP];          // packed fp16x2 H
__device__ uint32_t g_Xp[(size_t)TOK * XKP];               // packed fp16x2 X
__device__ uint32_t g_W1p[(size_t)NGRP * XKP * D_FF];      // [g][kp][f]
__device__ uint32_t g_W2p[(size_t)NGRP * HKP * D_MODEL];   // [g][kp][d]
__device__ int   g_count[N_EXPERTS + 1];
__device__ int   g_offset[N_EXPERTS + 2];
__device__ int   g_cursor[N_EXPERTS];
__device__ int   g_tok_e0[TOK];
__device__ int   g_tok_e1[TOK];
__device__ float g_tok_p0[TOK];
__device__ float g_tok_p1[TOK];
__device__ float g_tok_om[TOK];
__device__ int   g_assign_tok[TOT_ROWS];
__device__ float g_assign_w[TOT_ROWS];

// ----------------------------- helpers -------------------------------------
__device__ __forceinline__ void mma16816(float d[4], const uint32_t a[4],
                                         uint32_t b0, uint32_t b1) {
    asm volatile(
        "mma.sync.aligned.m16n8k16.row.col.f32.f16.f16.f32 "
        "{%0,%1,%2,%3}, {%4,%5,%6,%7}, {%8,%9}, {%0,%1,%2,%3};"
        : "+f"(d[0]), "+f"(d[1]), "+f"(d[2]), "+f"(d[3])
        : "r"(a[0]), "r"(a[1]), "r"(a[2]), "r"(a[3]), "r"(b0), "r"(b1));
}
__device__ __forceinline__ uint32_t pack2h(float x, float y) {
    __half2 h = __floats2half2_rn(x, y);
    return *(uint32_t*)&h;
}

// ----------------------------- prep: zero out + pack W1/W2 -----------------
#define ZB  (OUT_ELEMS / 4 / 256)               // 4096 blocks
#define W1B (NGRP * XKP * D_FF / 256)           // 18432 blocks
#define W2B (NGRP * HKP * D_MODEL / 256)        // 18432 blocks

__global__ void k_prep(float4* __restrict__ out4,
                       const float* __restrict__ w1, const float* __restrict__ uw1,
                       const float* __restrict__ w2, const float* __restrict__ uw2) {
    const int b   = blockIdx.x;
    const int tid = threadIdx.x;
    if (b < ZB) {
        out4[b * 256 + tid] = make_float4(0.f, 0.f, 0.f, 0.f);
        if (b == 0 && tid <= N_EXPERTS) g_count[tid] = 0;
    } else if (b < ZB + W1B) {
        const unsigned j  = (unsigned)(b - ZB) * 256u + tid;
        const unsigned e  = j / (unsigned)(XKP * D_FF);
        const unsigned r  = j % (unsigned)(XKP * D_FF);
        const unsigned kp = r / (unsigned)D_FF, n = r % (unsigned)D_FF;
        const float* src = (e < N_EXPERTS) ? (w1 + (size_t)e * D_MODEL * D_FF) : uw1;
        g_W1p[j] = pack2h(src[(size_t)(2 * kp) * D_FF + n],
                          src[(size_t)(2 * kp + 1) * D_FF + n]);
    } else {
        const unsigned j  = (unsigned)(b - ZB - W1B) * 256u + tid;
        const unsigned e  = j / (unsigned)(HKP * D_MODEL);
        const unsigned r  = j % (unsigned)(HKP * D_MODEL);
        const unsigned kp = r / (unsigned)D_MODEL, n = r % (unsigned)D_MODEL;
        const float* src = (e < N_EXPERTS) ? (w2 + (size_t)e * D_FF * D_MODEL) : uw2;
        g_W2p[j] = pack2h(src[(size_t)(2 * kp) * D_MODEL + n],
                          src[(size_t)(2 * kp + 1) * D_MODEL + n]);
    }
}

// ----------------------------- gating (+ X packing) ------------------------
__global__ void k_gate(const float* __restrict__ x,
                       const int*   __restrict__ task_ids,
                       const float* __restrict__ temb,
                       const float* __restrict__ gw,
                       const float* __restrict__ gb,
                       float* __restrict__ out_logits) {
    const int t   = blockIdx.x;
    const int tid = threadIdx.x;
    const int task = task_ids[t / SEQ];
    const float* xr = x    + (size_t)t    * D_MODEL;
    const float* tr = temb + (size_t)task * D_MODEL;

    // pack this token's x row: 256 k-pairs, one per thread
    {
        float2 xv = *(const float2*)(xr + 2 * tid);
        g_Xp[(size_t)t * XKP + tid] = pack2h(xv.x, xv.y);
    }

    float acc[N_EXPERTS];
#pragma unroll
    for (int e = 0; e < N_EXPERTS; e++) acc[e] = 0.f;
    for (int d = tid; d < 2 * D_MODEL; d += 256) {
        float v = (d < D_MODEL) ? xr[d] : tr[d - D_MODEL];
        const float* g = gw + (size_t)d * N_EXPERTS;
#pragma unroll
        for (int e = 0; e < N_EXPERTS; e++) acc[e] += v * g[e];
    }
#pragma unroll
    for (int e = 0; e < N_EXPERTS; e++)
#pragma unroll
        for (int off = 16; off > 0; off >>= 1)
            acc[e] += __shfl_down_sync(0xffffffffu, acc[e], off);

    __shared__ float s_acc[8][N_EXPERTS];
    const int warp = tid >> 5, lane = tid & 31;
    if (lane == 0)
#pragma unroll
        for (int e = 0; e < N_EXPERTS; e++) s_acc[warp][e] = acc[e];
    __syncthreads();

    if (tid == 0) {
        float lg[N_EXPERTS];
#pragma unroll
        for (int e = 0; e < N_EXPERTS; e++) {
            float s = gb[e];
#pragma unroll
            for (int w = 0; w < 8; w++) s += s_acc[w][e];
            lg[e] = s;
            out_logits[(size_t)t * N_EXPERTS + e] = s;
        }
        int e0 = 0; float v0 = lg[0];
#pragma unroll
        for (int e = 1; e < N_EXPERTS; e++) if (lg[e] > v0) { v0 = lg[e]; e0 = e; }
        int e1 = -1; float v1 = -1e30f;
#pragma unroll
        for (int e = 0; e < N_EXPERTS; e++)
            if (e != e0 && lg[e] > v1) { v1 = lg[e]; e1 = e; }
        float ex = expf(v1 - v0);
        float p0 = 1.f / (1.f + ex);
        g_tok_e0[t] = e0;  g_tok_e1[t] = e1;
        g_tok_p0[t] = p0;  g_tok_p1[t] = ex / (1.f + ex);
        g_tok_om[t] = 1.f - p0;
        atomicAdd(&g_count[e0], 1);
        atomicAdd(&g_count[e1], 1);
    }
}

__global__ void k_scan() {
    if (blockIdx.x == 0 && threadIdx.x == 0) {
        int o = 0;
        for (int e = 0; e < N_EXPERTS; e++) { g_offset[e] = o; g_cursor[e] = o; o += g_count[e]; }
        g_offset[N_EXPERTS]     = o;
        g_offset[N_EXPERTS + 1] = o + TOK;
    }
}

// atomic placement (row order within an expert is irrelevant to values)
__global__ void k_place() {
    const int t = blockIdx.x * 256 + threadIdx.x;
    const int e0 = g_tok_e0[t], e1 = g_tok_e1[t];
    const int p0pos = atomicAdd(&g_cursor[e0], 1);
    g_assign_tok[p0pos] = t;  g_assign_w[p0pos] = g_tok_p0[t];
    const int p1pos = atomicAdd(&g_cursor[e1], 1);
    g_assign_tok[p1pos] = t;  g_assign_w[p1pos] = g_tok_p1[t];
    const int ub = g_offset[N_EXPERTS] + t;
    g_assign_tok[ub] = t;     g_assign_w[ub] = g_tok_om[t];
}

// ---------------------------------------------------------------------------
// MMA over one BK=16 chunk: plain fp16 A and B, packed fp16x2 in smem.
// 8 warps (2x4), warp tile 64x32; g = lane>>2 (row/col), c = lane&3 (k-pair).
// ---------------------------------------------------------------------------
__device__ __forceinline__ void mma_chunk(float d[4][4][4],
                                          const uint32_t* Ah, const uint32_t* Bh,
                                          int wm, int wn, int g, int c) {
    uint32_t ah[4][4];
#pragma unroll
    for (int mt = 0; mt < 4; mt++) {
        const int r0 = (wm * 64 + mt * 16 + g) * ASTRIDE;
        const int r1 = r0 + 8 * ASTRIDE;
        ah[mt][0] = Ah[r0 + c];
        ah[mt][1] = Ah[r1 + c];
        ah[mt][2] = Ah[r0 + c + 4];
        ah[mt][3] = Ah[r1 + c + 4];
    }
    uint32_t bh[4][2];
#pragma unroll
    for (int nt = 0; nt < 4; nt++) {
        const int n = wn * 32 + nt * 8 + g;
        bh[nt][0] = Bh[c * BSTRIDE + n];
        bh[nt][1] = Bh[(c + 4) * BSTRIDE + n];
    }
#pragma unroll
    for (int mt = 0; mt < 4; mt++)
#pragma unroll
        for (int nt = 0; nt < 4; nt++)
            mma16816(d[mt][nt], ah[mt], bh[nt][0], bh[nt][1]);
}

#define AWORDS (128 * ASTRIDE)   // 1536
#define BWORDS (8 * BSTRIDE)     // 1088

// ----------------------------- FFN1: H = gelu(X @ W1 + b1) -----------------
// grid (D_FF/128, 64, 9), 256 threads, 2-stage double buffer.
__global__ void __launch_bounds__(256)
k_ffn1(const float* __restrict__ b1, const float* __restrict__ ub1) {
    const int z    = blockIdx.z;
    const int roff = g_offset[z];
    const int cnt  = g_offset[z + 1] - roff;
    const int m0   = blockIdx.y * 128;
    if (m0 >= cnt) return;
    const int f0   = blockIdx.x * 128;

    const uint32_t* __restrict__ Wp = g_W1p + (size_t)z * XKP * D_FF;
    const float* __restrict__ bias  = (z < N_EXPERTS) ? (b1 + (size_t)z * D_FF) : ub1;

    __shared__ int      s_tok[128];
    __shared__ uint32_t As_h[2][AWORDS];
    __shared__ uint32_t Bs_h[2][BWORDS];

    const int tid  = threadIdx.x;
    const int wid  = tid >> 5;
    const int lane = tid & 31;
    const int wm = wid >> 2, wn = wid & 3;
    const int g = lane >> 2, c = lane & 3;

    if (tid < 128) {
        const int mm = m0 + tid;
        s_tok[tid] = g_assign_tok[roff + ((mm < cnt) ? mm : 0)];
    }
    __syncthreads();

    int   rA[4], kpA[4], kpB[4], fB[4];
    unsigned arow[4];
#pragma unroll
    for (int q = 0; q < 4; q++) {
        const int ia = tid + q * 256;
        rA[q]  = ia >> 3;  kpA[q] = ia & 7;
        arow[q] = (unsigned)s_tok[rA[q]] * (unsigned)XKP;
        kpB[q] = ia >> 7;  fB[q]  = ia & 127;
    }

    float d[4][4][4];
#pragma unroll
    for (int a = 0; a < 4; a++)
#pragma unroll
        for (int b = 0; b < 4; b++)
#pragma unroll
            for (int e = 0; e < 4; e++) d[a][b][e] = 0.f;

    uint32_t pa[4], pb[4];
#pragma unroll
    for (int q = 0; q < 4; q++) {
        pa[q] = g_Xp[(size_t)arow[q] + kpA[q]];
        pb[q] = Wp[(size_t)kpB[q] * D_FF + f0 + fB[q]];
    }

    constexpr int NCH = D_MODEL / 16;   // 32 chunks of 8 k-pairs
    for (int ch = 0; ch < NCH; ch++) {
        const int buf = ch & 1;
#pragma unroll
        for (int q = 0; q < 4; q++) {
            As_h[buf][rA[q] * ASTRIDE + kpA[q]] = pa[q];
            Bs_h[buf][kpB[q] * BSTRIDE + fB[q]] = pb[q];
        }
        if (ch + 1 < NCH) {
            const int kp0 = (ch + 1) * 8;
#pragma unroll
            for (int q = 0; q < 4; q++) {
                pa[q] = g_Xp[(size_t)arow[q] + kp0 + kpA[q]];
                pb[q] = Wp[(size_t)(kp0 + kpB[q]) * D_FF + f0 + fB[q]];
            }
        }
        __syncthreads();
        mma_chunk(d, As_h[buf], Bs_h[buf], wm, wn, g, c);
    }

    // epilogue: bias + exact gelu -> packed fp16 H
#pragma unroll
    for (int mt = 0; mt < 4; mt++)
#pragma unroll
        for (int half = 0; half < 2; half++) {
            const int m = wm * 64 + mt * 16 + g + half * 8;
            if (m0 + m >= cnt) continue;
            const size_t hbase = (size_t)(roff + m0 + m) * HKP;
#pragma unroll
            for (int nt = 0; nt < 4; nt++) {
                const int f = f0 + wn * 32 + nt * 8 + 2 * c;
                float v0 = d[mt][nt][half * 2 + 0] + bias[f];
                float v1 = d[mt][nt][half * 2 + 1] + bias[f + 1];
                v0 = 0.5f * v0 * (1.0f + erff(v0 * 0.70710678118654752f));
                v1 = 0.5f * v1 * (1.0f + erff(v1 * 0.70710678118654752f));
                g_Hh[hbase + (f >> 1)] = pack2h(v0, v1);
            }
        }
}

// ----------------------------- FFN2: out += w*(H @ W2 + b2) ----------------
// grid (D_MODEL/128, 64, 9), 2-stage double buffer.
__global__ void __launch_bounds__(256)
k_ffn2(float* __restrict__ out,
       const float* __restrict__ b2, const float* __restrict__ ub2) {
    const int z    = blockIdx.z;
    const int roff = g_offset[z];
    const int cnt  = g_offset[z + 1] - roff;
    const int m0   = blockIdx.y * 128;
    if (m0 >= cnt) return;
    const int d0   = blockIdx.x * 128;

    const uint32_t* __restrict__ Wp = g_W2p + (size_t)z * HKP * D_MODEL;
    const float* __restrict__ bias  = (z < N_EXPERTS) ? (b2 + (size_t)z * D_MODEL) : ub2;

    __shared__ int      s_tok[128];
    __shared__ float    s_w[128];
    __shared__ uint32_t As_h[2][AWORDS];
    __shared__ uint32_t Bs_h[2][BWORDS];

    const int tid  = threadIdx.x;
    const int wid  = tid >> 5;
    const int lane = tid & 31;
    const int wm = wid >> 2, wn = wid & 3;
    const int g = lane >> 2, c = lane & 3;

    if (tid < 128) {
        const int mm = m0 + tid;
        const int rr = roff + ((mm < cnt) ? mm : 0);
        s_tok[tid] = g_assign_tok[rr];
        s_w[tid]   = g_assign_w[rr];
    }
    __syncthreads();

    int   rA[4], kpA[4], kpB[4], fB[4];
    size_t arowp[4];
#pragma unroll
    for (int q = 0; q < 4; q++) {
        const int ia = tid + q * 256;
        rA[q]  = ia >> 3;  kpA[q] = ia & 7;
        const int mm = m0 + rA[q];
        arowp[q] = (size_t)(roff + ((mm < cnt) ? mm : m0)) * HKP;
        kpB[q] = ia >> 7;  fB[q]  = ia & 127;
    }

    float d[4][4][4];
#pragma unroll
    for (int a = 0; a < 4; a++)
#pragma unroll
        for (int b = 0; b < 4; b++)
#pragma unroll
            for (int e = 0; e < 4; e++) d[a][b][e] = 0.f;

    uint32_t pa[4], pb[4];
#pragma unroll
    for (int q = 0; q < 4; q++) {
        pa[q] = g_Hh[arowp[q] + kpA[q]];
        pb[q] = Wp[(size_t)kpB[q] * D_MODEL + d0 + fB[q]];
    }

    constexpr int NCH = D_FF / 16;   // 128 chunks of 8 k-pairs
    for (int ch = 0; ch < NCH; ch++) {
        const int buf = ch & 1;
#pragma unroll
        for (int q = 0; q < 4; q++) {
            As_h[buf][rA[q] * ASTRIDE + kpA[q]] = pa[q];
            Bs_h[buf][kpB[q] * BSTRIDE + fB[q]] = pb[q];
        }
        if (ch + 1 < NCH) {
            const int kp0 = (ch + 1) * 8;
#pragma unroll
            for (int q = 0; q < 4; q++) {
                pa[q] = g_Hh[arowp[q] + kp0 + kpA[q]];
                pb[q] = Wp[(size_t)(kp0 + kpB[q]) * D_MODEL + d0 + fB[q]];
            }
        }
        __syncthreads();
        mma_chunk(d, As_h[buf], Bs_h[buf], wm, wn, g, c);
    }

    // epilogue: weighted atomic accumulation
#pragma unroll
    for (int mt = 0; mt < 4; mt++)
#pragma unroll
        for (int half = 0; half < 2; half++) {
            const int m = wm * 64 + mt * 16 + g + half * 8;
            if (m0 + m >= cnt) continue;
            const int   tok = s_tok[m];
            const float wr  = s_w[m];
            float* orow = out + (size_t)tok * D_MODEL;
#pragma unroll
            for (int nt = 0; nt < 4; nt++) {
                const int dd = d0 + wn * 32 + nt * 8 + 2 * c;
                atomicAdd(&orow[dd],     wr * (d[mt][nt][half * 2 + 0] + bias[dd]));
                atomicAdd(&orow[dd + 1], wr * (d[mt][nt][half * 2 + 1] + bias[dd + 1]));
            }
        }
}

// ----------------------------- launch --------------------------------------
extern "C" void kernel_launch(void* const* d_in, const int* in_sizes, int n_in,
                              void* d_out, int out_size) {
    const float* x        = (const float*)d_in[0];
    const int*   task_ids = (const int*)  d_in[1];
    const float* temb     = (const float*)d_in[2];
    const float* gw       = (const float*)d_in[3];
    const float* gb       = (const float*)d_in[4];
    const float* w1       = (const float*)d_in[5];
    const float* b1       = (const float*)d_in[6];
    const float* w2       = (const float*)d_in[7];
    const float* b2       = (const float*)d_in[8];
    const float* uw1      = (const float*)d_in[9];
    const float* ub1      = (const float*)d_in[10];
    const float* uw2      = (const float*)d_in[11];
    const float* ub2      = (const float*)d_in[12];

    float* out        = (float*)d_out;
    float* out_logits = out + OUT_ELEMS;

    k_prep<<<ZB + W1B + W2B, 256>>>((float4*)out, w1, uw1, w2, uw2);
    k_gate<<<TOK, 256>>>(x, task_ids, temb, gw, gb, out_logits);
    k_scan<<<1, 32>>>();
    k_place<<<TOK / 256, 256>>>();
    k_ffn1<<<dim3(D_FF / 128, TOK / 128, NGRP), 256>>>(b1, ub1);
    k_ffn2<<<dim3(D_MODEL / 128, TOK / 128, NGRP), 256>>>(out, b2, ub2);
}

// round 12
// speedup vs baseline: 1.0029x; 1.0029x over previous
#include <cuda_runtime.h>
#include <cuda_fp16.h>
#include <math.h>
#include <stdint.h>

// ---------------------------------------------------------------------------
// TaskAwareMoE round 12: identical to round 11 except __launch_bounds__(256,2)
// on both FFN kernels (2 CTAs/SM to cover barrier + LDG latency).
// ---------------------------------------------------------------------------

#define D_MODEL   512
#define D_FF      2048
#define N_EXPERTS 8
#define BATCH     8
#define SEQ       1024
#define TOK       (BATCH * SEQ)            // 8192
#define EXP_ROWS  (2 * TOK)                // 16384
#define TOT_ROWS  (EXP_ROWS + TOK)         // 24576
#define OUT_ELEMS (TOK * D_MODEL)          // 4,194,304
#define NGRP      (N_EXPERTS + 1)
#define XKP       (D_MODEL / 2)            // 256 k-pairs per X row
#define HKP       (D_FF / 2)               // 1024 k-pairs per H row

#define ASTRIDE 12      // uint32 words per A row  (8 used + 4 pad) -> bank-free
#define BSTRIDE 136     // uint32 words per B k-pair row (128 used + 8 pad)

// ----------------------------- static scratch ------------------------------
__device__ uint32_t g_Hh[(size_t)TOT_ROWS * HKP];          // packed fp16x2 H
__device__ uint32_t g_Xp[(size_t)TOK * XKP];               // packed fp16x2 X
__device__ uint32_t g_W1p[(size_t)NGRP * XKP * D_FF];      // [g][kp][f]
__device__ uint32_t g_W2p[(size_t)NGRP * HKP * D_MODEL];   // [g][kp][d]
__device__ int   g_count[N_EXPERTS + 1];
__device__ int   g_offset[N_EXPERTS + 2];
__device__ int   g_cursor[N_EXPERTS];
__device__ int   g_tok_e0[TOK];
__device__ int   g_tok_e1[TOK];
__device__ float g_tok_p0[TOK];
__device__ float g_tok_p1[TOK];
__device__ float g_tok_om[TOK];
__device__ int   g_assign_tok[TOT_ROWS];
__device__ float g_assign_w[TOT_ROWS];

// ----------------------------- helpers -------------------------------------
__device__ __forceinline__ void mma16816(float d[4], const uint32_t a[4],
                                         uint32_t b0, uint32_t b1) {
    asm volatile(
        "mma.sync.aligned.m16n8k16.row.col.f32.f16.f16.f32 "
        "{%0,%1,%2,%3}, {%4,%5,%6,%7}, {%8,%9}, {%0,%1,%2,%3};"
        : "+f"(d[0]), "+f"(d[1]), "+f"(d[2]), "+f"(d[3])
        : "r"(a[0]), "r"(a[1]), "r"(a[2]), "r"(a[3]), "r"(b0), "r"(b1));
}
__device__ __forceinline__ uint32_t pack2h(float x, float y) {
    __half2 h = __floats2half2_rn(x, y);
    return *(uint32_t*)&h;
}

// ----------------------------- prep: zero out + pack W1/W2 -----------------
#define ZB  (OUT_ELEMS / 4 / 256)               // 4096 blocks
#define W1B (NGRP * XKP * D_FF / 256)           // 18432 blocks
#define W2B (NGRP * HKP * D_MODEL / 256)        // 18432 blocks

__global__ void k_prep(float4* __restrict__ out4,
                       const float* __restrict__ w1, const float* __restrict__ uw1,
                       const float* __restrict__ w2, const float* __restrict__ uw2) {
    const int b   = blockIdx.x;
    const int tid = threadIdx.x;
    if (b < ZB) {
        out4[b * 256 + tid] = make_float4(0.f, 0.f, 0.f, 0.f);
        if (b == 0 && tid <= N_EXPERTS) g_count[tid] = 0;
    } else if (b < ZB + W1B) {
        const unsigned j  = (unsigned)(b - ZB) * 256u + tid;
        const unsigned e  = j / (unsigned)(XKP * D_FF);
        const unsigned r  = j % (unsigned)(XKP * D_FF);
        const unsigned kp = r / (unsigned)D_FF, n = r % (unsigned)D_FF;
        const float* src = (e < N_EXPERTS) ? (w1 + (size_t)e * D_MODEL * D_FF) : uw1;
        g_W1p[j] = pack2h(src[(size_t)(2 * kp) * D_FF + n],
                          src[(size_t)(2 * kp + 1) * D_FF + n]);
    } else {
        const unsigned j  = (unsigned)(b - ZB - W1B) * 256u + tid;
        const unsigned e  = j / (unsigned)(HKP * D_MODEL);
        const unsigned r  = j % (unsigned)(HKP * D_MODEL);
        const unsigned kp = r / (unsigned)D_MODEL, n = r % (unsigned)D_MODEL;
        const float* src = (e < N_EXPERTS) ? (w2 + (size_t)e * D_FF * D_MODEL) : uw2;
        g_W2p[j] = pack2h(src[(size_t)(2 * kp) * D_MODEL + n],
                          src[(size_t)(2 * kp + 1) * D_MODEL + n]);
    }
}

// ----------------------------- gating (+ X packing) ------------------------
__global__ void k_gate(const float* __restrict__ x,
                       const int*   __restrict__ task_ids,
                       const float* __restrict__ temb,
                       const float* __restrict__ gw,
                       const float* __restrict__ gb,
                       float* __restrict__ out_logits) {
    const int t   = blockIdx.x;
    const int tid = threadIdx.x;
    const int task = task_ids[t / SEQ];
    const float* xr = x    + (size_t)t    * D_MODEL;
    const float* tr = temb + (size_t)task * D_MODEL;

    // pack this token's x row: 256 k-pairs, one per thread
    {
        float2 xv = *(const float2*)(xr + 2 * tid);
        g_Xp[(size_t)t * XKP + tid] = pack2h(xv.x, xv.y);
    }

    float acc[N_EXPERTS];
#pragma unroll
    for (int e = 0; e < N_EXPERTS; e++) acc[e] = 0.f;
    for (int d = tid; d < 2 * D_MODEL; d += 256) {
        float v = (d < D_MODEL) ? xr[d] : tr[d - D_MODEL];
        const float* g = gw + (size_t)d * N_EXPERTS;
#pragma unroll
        for (int e = 0; e < N_EXPERTS; e++) acc[e] += v * g[e];
    }
#pragma unroll
    for (int e = 0; e < N_EXPERTS; e++)
#pragma unroll
        for (int off = 16; off > 0; off >>= 1)
            acc[e] += __shfl_down_sync(0xffffffffu, acc[e], off);

    __shared__ float s_acc[8][N_EXPERTS];
    const int warp = tid >> 5, lane = tid & 31;
    if (lane == 0)
#pragma unroll
        for (int e = 0; e < N_EXPERTS; e++) s_acc[warp][e] = acc[e];
    __syncthreads();

    if (tid == 0) {
        float lg[N_EXPERTS];
#pragma unroll
        for (int e = 0; e < N_EXPERTS; e++) {
            float s = gb[e];
#pragma unroll
            for (int w = 0; w < 8; w++) s += s_acc[w][e];
            lg[e] = s;
            out_logits[(size_t)t * N_EXPERTS + e] = s;
        }
        int e0 = 0; float v0 = lg[0];
#pragma unroll
        for (int e = 1; e < N_EXPERTS; e++) if (lg[e] > v0) { v0 = lg[e]; e0 = e; }
        int e1 = -1; float v1 = -1e30f;
#pragma unroll
        for (int e = 0; e < N_EXPERTS; e++)
            if (e != e0 && lg[e] > v1) { v1 = lg[e]; e1 = e; }
        float ex = expf(v1 - v0);
        float p0 = 1.f / (1.f + ex);
        g_tok_e0[t] = e0;  g_tok_e1[t] = e1;
        g_tok_p0[t] = p0;  g_tok_p1[t] = ex / (1.f + ex);
        g_tok_om[t] = 1.f - p0;
        atomicAdd(&g_count[e0], 1);
        atomicAdd(&g_count[e1], 1);
    }
}

__global__ void k_scan() {
    if (blockIdx.x == 0 && threadIdx.x == 0) {
        int o = 0;
        for (int e = 0; e < N_EXPERTS; e++) { g_offset[e] = o; g_cursor[e] = o; o += g_count[e]; }
        g_offset[N_EXPERTS]     = o;
        g_offset[N_EXPERTS + 1] = o + TOK;
    }
}

// atomic placement (row order within an expert is irrelevant to values)
__global__ void k_place() {
    const int t = blockIdx.x * 256 + threadIdx.x;
    const int e0 = g_tok_e0[t], e1 = g_tok_e1[t];
    const int p0pos = atomicAdd(&g_cursor[e0], 1);
    g_assign_tok[p0pos] = t;  g_assign_w[p0pos] = g_tok_p0[t];
    const int p1pos = atomicAdd(&g_cursor[e1], 1);
    g_assign_tok[p1pos] = t;  g_assign_w[p1pos] = g_tok_p1[t];
    const int ub = g_offset[N_EXPERTS] + t;
    g_assign_tok[ub] = t;     g_assign_w[ub] = g_tok_om[t];
}

// ---------------------------------------------------------------------------
// MMA over one BK=16 chunk: plain fp16 A and B, packed fp16x2 in smem.
// 8 warps (2x4), warp tile 64x32; g = lane>>2 (row/col), c = lane&3 (k-pair).
// ---------------------------------------------------------------------------
__device__ __forceinline__ void mma_chunk(float d[4][4][4],
                                          const uint32_t* Ah, const uint32_t* Bh,
                                          int wm, int wn, int g, int c) {
    uint32_t ah[4][4];
#pragma unroll
    for (int mt = 0; mt < 4; mt++) {
        const int r0 = (wm * 64 + mt * 16 + g) * ASTRIDE;
        const int r1 = r0 + 8 * ASTRIDE;
        ah[mt][0] = Ah[r0 + c];
        ah[mt][1] = Ah[r1 + c];
        ah[mt][2] = Ah[r0 + c + 4];
        ah[mt][3] = Ah[r1 + c + 4];
    }
    uint32_t bh[4][2];
#pragma unroll
    for (int nt = 0; nt < 4; nt++) {
        const int n = wn * 32 + nt * 8 + g;
        bh[nt][0] = Bh[c * BSTRIDE + n];
        bh[nt][1] = Bh[(c + 4) * BSTRIDE + n];
    }
#pragma unroll
    for (int mt = 0; mt < 4; mt++)
#pragma unroll
        for (int nt = 0; nt < 4; nt++)
            mma16816(d[mt][nt], ah[mt], bh[nt][0], bh[nt][1]);
}

#define AWORDS (128 * ASTRIDE)   // 1536
#define BWORDS (8 * BSTRIDE)     // 1088

// ----------------------------- FFN1: H = gelu(X @ W1 + b1) -----------------
// grid (D_FF/128, 64, 9), 256 threads, 2-stage double buffer, 2 CTAs/SM.
__global__ void __launch_bounds__(256, 2)
k_ffn1(const float* __restrict__ b1, const float* __restrict__ ub1) {
    const int z    = blockIdx.z;
    const int roff = g_offset[z];
    const int cnt  = g_offset[z + 1] - roff;
    const int m0   = blockIdx.y * 128;
    if (m0 >= cnt) return;
    const int f0   = blockIdx.x * 128;

    const uint32_t* __restrict__ Wp = g_W1p + (size_t)z * XKP * D_FF;
    const float* __restrict__ bias  = (z < N_EXPERTS) ? (b1 + (size_t)z * D_FF) : ub1;

    __shared__ int      s_tok[128];
    __shared__ uint32_t As_h[2][AWORDS];
    __shared__ uint32_t Bs_h[2][BWORDS];

    const int tid  = threadIdx.x;
    const int wid  = tid >> 5;
    const int lane = tid & 31;
    const int wm = wid >> 2, wn = wid & 3;
    const int g = lane >> 2, c = lane & 3;

    if (tid < 128) {
        const int mm = m0 + tid;
        s_tok[tid] = g_assign_tok[roff + ((mm < cnt) ? mm : 0)];
    }
    __syncthreads();

    int   rA[4], kpA[4], kpB[4], fB[4];
    unsigned arow[4];
#pragma unroll
    for (int q = 0; q < 4; q++) {
        const int ia = tid + q * 256;
        rA[q]  = ia >> 3;  kpA[q] = ia & 7;
        arow[q] = (unsigned)s_tok[rA[q]] * (unsigned)XKP;
        kpB[q] = ia >> 7;  fB[q]  = ia & 127;
    }

    float d[4][4][4];
#pragma unroll
    for (int a = 0; a < 4; a++)
#pragma unroll
        for (int b = 0; b < 4; b++)
#pragma unroll
            for (int e = 0; e < 4; e++) d[a][b][e] = 0.f;

    uint32_t pa[4], pb[4];
#pragma unroll
    for (int q = 0; q < 4; q++) {
        pa[q] = g_Xp[(size_t)arow[q] + kpA[q]];
        pb[q] = Wp[(size_t)kpB[q] * D_FF + f0 + fB[q]];
    }

    constexpr int NCH = D_MODEL / 16;   // 32 chunks of 8 k-pairs
    for (int ch = 0; ch < NCH; ch++) {
        const int buf = ch & 1;
#pragma unroll
        for (int q = 0; q < 4; q++) {
            As_h[buf][rA[q] * ASTRIDE + kpA[q]] = pa[q];
            Bs_h[buf][kpB[q] * BSTRIDE + fB[q]] = pb[q];
        }
        if (ch + 1 < NCH) {
            const int kp0 = (ch + 1) * 8;
#pragma unroll
            for (int q = 0; q < 4; q++) {
                pa[q] = g_Xp[(size_t)arow[q] + kp0 + kpA[q]];
                pb[q] = Wp[(size_t)(kp0 + kpB[q]) * D_FF + f0 + fB[q]];
            }
        }
        __syncthreads();
        mma_chunk(d, As_h[buf], Bs_h[buf], wm, wn, g, c);
    }

    // epilogue: bias + exact gelu -> packed fp16 H
#pragma unroll
    for (int mt = 0; mt < 4; mt++)
#pragma unroll
        for (int half = 0; half < 2; half++) {
            const int m = wm * 64 + mt * 16 + g + half * 8;
            if (m0 + m >= cnt) continue;
            const size_t hbase = (size_t)(roff + m0 + m) * HKP;
#pragma unroll
            for (int nt = 0; nt < 4; nt++) {
                const int f = f0 + wn * 32 + nt * 8 + 2 * c;
                float v0 = d[mt][nt][half * 2 + 0] + bias[f];
                float v1 = d[mt][nt][half * 2 + 1] + bias[f + 1];
                v0 = 0.5f * v0 * (1.0f + erff(v0 * 0.70710678118654752f));
                v1 = 0.5f * v1 * (1.0f + erff(v1 * 0.70710678118654752f));
                g_Hh[hbase + (f >> 1)] = pack2h(v0, v1);
            }
        }
}

// ----------------------------- FFN2: out += w*(H @ W2 + b2) ----------------
// grid (D_MODEL/128, 64, 9), 2-stage double buffer, 2 CTAs/SM.
__global__ void __launch_bounds__(256, 2)
k_ffn2(float* __restrict__ out,
       const float* __restrict__ b2, const float* __restrict__ ub2) {
    const int z    = blockIdx.z;
    const int roff = g_offset[z];
    const int cnt  = g_offset[z + 1] - roff;
    const int m0   = blockIdx.y * 128;
    if (m0 >= cnt) return;
    const int d0   = blockIdx.x * 128;

    const uint32_t* __restrict__ Wp = g_W2p + (size_t)z * HKP * D_MODEL;
    const float* __restrict__ bias  = (z < N_EXPERTS) ? (b2 + (size_t)z * D_MODEL) : ub2;

    __shared__ int      s_tok[128];
    __shared__ float    s_w[128];
    __shared__ uint32_t As_h[2][AWORDS];
    __shared__ uint32_t Bs_h[2][BWORDS];

    const int tid  = threadIdx.x;
    const int wid  = tid >> 5;
    const int lane = tid & 31;
    const int wm = wid >> 2, wn = wid & 3;
    const int g = lane >> 2, c = lane & 3;

    if (tid < 128) {
        const int mm = m0 + tid;
        const int rr = roff + ((mm < cnt) ? mm : 0);
        s_tok[tid] = g_assign_tok[rr];
        s_w[tid]   = g_assign_w[rr];
    }
    __syncthreads();

    int   rA[4], kpA[4], kpB[4], fB[4];
    size_t arowp[4];
#pragma unroll
    for (int q = 0; q < 4; q++) {
        const int ia = tid + q * 256;
        rA[q]  = ia >> 3;  kpA[q] = ia & 7;
        const int mm = m0 + rA[q];
        arowp[q] = (size_t)(roff + ((mm < cnt) ? mm : m0)) * HKP;
        kpB[q] = ia >> 7;  fB[q]  = ia & 127;
    }

    float d[4][4][4];
#pragma unroll
    for (int a = 0; a < 4; a++)
#pragma unroll
        for (int b = 0; b < 4; b++)
#pragma unroll
            for (int e = 0; e < 4; e++) d[a][b][e] = 0.f;

    uint32_t pa[4], pb[4];
#pragma unroll
    for (int q = 0; q < 4; q++) {
        pa[q] = g_Hh[arowp[q] + kpA[q]];
        pb[q] = Wp[(size_t)kpB[q] * D_MODEL + d0 + fB[q]];
    }

    constexpr int NCH = D_FF / 16;   // 128 chunks of 8 k-pairs
    for (int ch = 0; ch < NCH; ch++) {
        const int buf = ch & 1;
#pragma unroll
        for (int q = 0; q < 4; q++) {
            As_h[buf][rA[q] * ASTRIDE + kpA[q]] = pa[q];
            Bs_h[buf][kpB[q] * BSTRIDE + fB[q]] = pb[q];
        }
        if (ch + 1 < NCH) {
            const int kp0 = (ch + 1) * 8;
#pragma unroll
            for (int q = 0; q < 4; q++) {
                pa[q] = g_Hh[arowp[q] + kp0 + kpA[q]];
                pb[q] = Wp[(size_t)(kp0 + kpB[q]) * D_MODEL + d0 + fB[q]];
            }
        }
        __syncthreads();
        mma_chunk(d, As_h[buf], Bs_h[buf], wm, wn, g, c);
    }

    // epilogue: weighted atomic accumulation
#pragma unroll
    for (int mt = 0; mt < 4; mt++)
#pragma unroll
        for (int half = 0; half < 2; half++) {
            const int m = wm * 64 + mt * 16 + g + half * 8;
            if (m0 + m >= cnt) continue;
            const int   tok = s_tok[m];
            const float wr  = s_w[m];
            float* orow = out + (size_t)tok * D_MODEL;
#pragma unroll
            for (int nt = 0; nt < 4; nt++) {
                const int dd = d0 + wn * 32 + nt * 8 + 2 * c;
                atomicAdd(&orow[dd],     wr * (d[mt][nt][half * 2 + 0] + bias[dd]));
                atomicAdd(&orow[dd + 1], wr * (d[mt][nt][half * 2 + 1] + bias[dd + 1]));
            }
        }
}

// ----------------------------- launch --------------------------------------
extern "C" void kernel_launch(void* const* d_in, const int* in_sizes, int n_in,
                              void* d_out, int out_size) {
    const float* x        = (const float*)d_in[0];
    const int*   task_ids = (const int*)  d_in[1];
    const float* temb     = (const float*)d_in[2];
    const float* gw       = (const float*)d_in[3];
    const float* gb       = (const float*)d_in[4];
    const float* w1       = (const float*)d_in[5];
    const float* b1       = (const float*)d_in[6];
    const float* w2       = (const float*)d_in[7];
    const float* b2       = (const float*)d_in[8];
    const float* uw1      = (const float*)d_in[9];
    const float* ub1      = (const float*)d_in[10];
    const float* uw2      = (const float*)d_in[11];
    const float* ub2      = (const float*)d_in[12];

    float* out        = (float*)d_out;
    float* out_logits = out + OUT_ELEMS;

    k_prep<<<ZB + W1B + W2B, 256>>>((float4*)out, w1, uw1, w2, uw2);
    k_gate<<<TOK, 256>>>(x, task_ids, temb, gw, gb, out_logits);
    k_scan<<<1, 32>>>();
    k_place<<<TOK / 256, 256>>>();
    k_ffn1<<<dim3(D_FF / 128, TOK / 128, NGRP), 256>>>(b1, ub1);
    k_ffn2<<<dim3(D_MODEL / 128, TOK / 128, NGRP), 256>>>(out, b2, ub2);
}

// round 13
// speedup vs baseline: 1.1574x; 1.1541x over previous
#include <cuda_runtime.h>
#include <cuda_fp16.h>
#include <math.h>
#include <stdint.h>

// ---------------------------------------------------------------------------
// TaskAwareMoE round 13: BK=32 (half the chunks of round 11/12) to amortize
// per-chunk barrier/latency overhead. Same fp16 mma.sync math, same k order
// per accumulator -> output bit-identical to rounds 9/11/12.
// ---------------------------------------------------------------------------

#define D_MODEL   512
#define D_FF      2048
#define N_EXPERTS 8
#define BATCH     8
#define SEQ       1024
#define TOK       (BATCH * SEQ)            // 8192
#define EXP_ROWS  (2 * TOK)                // 16384
#define TOT_ROWS  (EXP_ROWS + TOK)         // 24576
#define OUT_ELEMS (TOK * D_MODEL)          // 4,194,304
#define NGRP      (N_EXPERTS + 1)
#define XKP       (D_MODEL / 2)            // 256 k-pairs per X row
#define HKP       (D_FF / 2)               // 1024 k-pairs per H row

#define ASTRIDE 20      // uint32 words per A row (16 used + 4 pad) -> bank-free
#define BSTRIDE 136     // uint32 words per B k-pair row (128 used + 8 pad)

// ----------------------------- static scratch ------------------------------
__device__ uint32_t g_Hh[(size_t)TOT_ROWS * HKP];          // packed fp16x2 H
__device__ uint32_t g_Xp[(size_t)TOK * XKP];               // packed fp16x2 X
__device__ uint32_t g_W1p[(size_t)NGRP * XKP * D_FF];      // [g][kp][f]
__device__ uint32_t g_W2p[(size_t)NGRP * HKP * D_MODEL];   // [g][kp][d]
__device__ int   g_count[N_EXPERTS + 1];
__device__ int   g_offset[N_EXPERTS + 2];
__device__ int   g_cursor[N_EXPERTS];
__device__ int   g_tok_e0[TOK];
__device__ int   g_tok_e1[TOK];
__device__ float g_tok_p0[TOK];
__device__ float g_tok_p1[TOK];
__device__ float g_tok_om[TOK];
__device__ int   g_assign_tok[TOT_ROWS];
__device__ float g_assign_w[TOT_ROWS];

// ----------------------------- helpers -------------------------------------
__device__ __forceinline__ void mma16816(float d[4], const uint32_t a[4],
                                         uint32_t b0, uint32_t b1) {
    asm volatile(
        "mma.sync.aligned.m16n8k16.row.col.f32.f16.f16.f32 "
        "{%0,%1,%2,%3}, {%4,%5,%6,%7}, {%8,%9}, {%0,%1,%2,%3};"
        : "+f"(d[0]), "+f"(d[1]), "+f"(d[2]), "+f"(d[3])
        : "r"(a[0]), "r"(a[1]), "r"(a[2]), "r"(a[3]), "r"(b0), "r"(b1));
}
__device__ __forceinline__ uint32_t pack2h(float x, float y) {
    __half2 h = __floats2half2_rn(x, y);
    return *(uint32_t*)&h;
}

// ----------------------------- prep: zero out + pack W1/W2 -----------------
#define ZB  (OUT_ELEMS / 4 / 256)               // 4096 blocks
#define W1B (NGRP * XKP * D_FF / 256)           // 18432 blocks
#define W2B (NGRP * HKP * D_MODEL / 256)        // 18432 blocks

__global__ void k_prep(float4* __restrict__ out4,
                       const float* __restrict__ w1, const float* __restrict__ uw1,
                       const float* __restrict__ w2, const float* __restrict__ uw2) {
    const int b   = blockIdx.x;
    const int tid = threadIdx.x;
    if (b < ZB) {
        out4[b * 256 + tid] = make_float4(0.f, 0.f, 0.f, 0.f);
        if (b == 0 && tid <= N_EXPERTS) g_count[tid] = 0;
    } else if (b < ZB + W1B) {
        const unsigned j  = (unsigned)(b - ZB) * 256u + tid;
        const unsigned e  = j / (unsigned)(XKP * D_FF);
        const unsigned r  = j % (unsigned)(XKP * D_FF);
        const unsigned kp = r / (unsigned)D_FF, n = r % (unsigned)D_FF;
        const float* src = (e < N_EXPERTS) ? (w1 + (size_t)e * D_MODEL * D_FF) : uw1;
        g_W1p[j] = pack2h(src[(size_t)(2 * kp) * D_FF + n],
                          src[(size_t)(2 * kp + 1) * D_FF + n]);
    } else {
        const unsigned j  = (unsigned)(b - ZB - W1B) * 256u + tid;
        const unsigned e  = j / (unsigned)(HKP * D_MODEL);
        const unsigned r  = j % (unsigned)(HKP * D_MODEL);
        const unsigned kp = r / (unsigned)D_MODEL, n = r % (unsigned)D_MODEL;
        const float* src = (e < N_EXPERTS) ? (w2 + (size_t)e * D_FF * D_MODEL) : uw2;
        g_W2p[j] = pack2h(src[(size_t)(2 * kp) * D_MODEL + n],
                          src[(size_t)(2 * kp + 1) * D_MODEL + n]);
    }
}

// ----------------------------- gating (+ X packing) ------------------------
__global__ void k_gate(const float* __restrict__ x,
                       const int*   __restrict__ task_ids,
                       const float* __restrict__ temb,
                       const float* __restrict__ gw,
                       const float* __restrict__ gb,
                       float* __restrict__ out_logits) {
    const int t   = blockIdx.x;
    const int tid = threadIdx.x;
    const int task = task_ids[t / SEQ];
    const float* xr = x    + (size_t)t    * D_MODEL;
    const float* tr = temb + (size_t)task * D_MODEL;

    {
        float2 xv = *(const float2*)(xr + 2 * tid);
        g_Xp[(size_t)t * XKP + tid] = pack2h(xv.x, xv.y);
    }

    float acc[N_EXPERTS];
#pragma unroll
    for (int e = 0; e < N_EXPERTS; e++) acc[e] = 0.f;
    for (int d = tid; d < 2 * D_MODEL; d += 256) {
        float v = (d < D_MODEL) ? xr[d] : tr[d - D_MODEL];
        const float* g = gw + (size_t)d * N_EXPERTS;
#pragma unroll
        for (int e = 0; e < N_EXPERTS; e++) acc[e] += v * g[e];
    }
#pragma unroll
    for (int e = 0; e < N_EXPERTS; e++)
#pragma unroll
        for (int off = 16; off > 0; off >>= 1)
            acc[e] += __shfl_down_sync(0xffffffffu, acc[e], off);

    __shared__ float s_acc[8][N_EXPERTS];
    const int warp = tid >> 5, lane = tid & 31;
    if (lane == 0)
#pragma unroll
        for (int e = 0; e < N_EXPERTS; e++) s_acc[warp][e] = acc[e];
    __syncthreads();

    if (tid == 0) {
        float lg[N_EXPERTS];
#pragma unroll
        for (int e = 0; e < N_EXPERTS; e++) {
            float s = gb[e];
#pragma unroll
            for (int w = 0; w < 8; w++) s += s_acc[w][e];
            lg[e] = s;
            out_logits[(size_t)t * N_EXPERTS + e] = s;
        }
        int e0 = 0; float v0 = lg[0];
#pragma unroll
        for (int e = 1; e < N_EXPERTS; e++) if (lg[e] > v0) { v0 = lg[e]; e0 = e; }
        int e1 = -1; float v1 = -1e30f;
#pragma unroll
        for (int e = 0; e < N_EXPERTS; e++)
            if (e != e0 && lg[e] > v1) { v1 = lg[e]; e1 = e; }
        float ex = expf(v1 - v0);
        float p0 = 1.f / (1.f + ex);
        g_tok_e0[t] = e0;  g_tok_e1[t] = e1;
        g_tok_p0[t] = p0;  g_tok_p1[t] = ex / (1.f + ex);
        g_tok_om[t] = 1.f - p0;
        atomicAdd(&g_count[e0], 1);
        atomicAdd(&g_count[e1], 1);
    }
}

__global__ void k_scan() {
    if (blockIdx.x == 0 && threadIdx.x == 0) {
        int o = 0;
        for (int e = 0; e < N_EXPERTS; e++) { g_offset[e] = o; g_cursor[e] = o; o += g_count[e]; }
        g_offset[N_EXPERTS]     = o;
        g_offset[N_EXPERTS + 1] = o + TOK;
    }
}

__global__ void k_place() {
    const int t = blockIdx.x * 256 + threadIdx.x;
    const int e0 = g_tok_e0[t], e1 = g_tok_e1[t];
    const int p0pos = atomicAdd(&g_cursor[e0], 1);
    g_assign_tok[p0pos] = t;  g_assign_w[p0pos] = g_tok_p0[t];
    const int p1pos = atomicAdd(&g_cursor[e1], 1);
    g_assign_tok[p1pos] = t;  g_assign_w[p1pos] = g_tok_p1[t];
    const int ub = g_offset[N_EXPERTS] + t;
    g_assign_tok[ub] = t;     g_assign_w[ub] = g_tok_om[t];
}

// ---------------------------------------------------------------------------
// MMA over one BK=32 chunk (two k16 slabs, in k order -> bit-identical accum).
// 8 warps (2x4), warp tile 64x32; g = lane>>2, c = lane&3.
// ---------------------------------------------------------------------------
__device__ __forceinline__ void mma_chunk32(float d[4][4][4],
                                            const uint32_t* Ah, const uint32_t* Bh,
                                            int wm, int wn, int g, int c) {
#pragma unroll
    for (int ks = 0; ks < 2; ks++) {
        const int kb = ks * 8;
        uint32_t ah[4][4];
#pragma unroll
        for (int mt = 0; mt < 4; mt++) {
            const int r0 = (wm * 64 + mt * 16 + g) * ASTRIDE + kb;
            const int r1 = r0 + 8 * ASTRIDE;
            ah[mt][0] = Ah[r0 + c];
            ah[mt][1] = Ah[r1 + c];
            ah[mt][2] = Ah[r0 + c + 4];
            ah[mt][3] = Ah[r1 + c + 4];
        }
        uint32_t bh[4][2];
#pragma unroll
        for (int nt = 0; nt < 4; nt++) {
            const int n = wn * 32 + nt * 8 + g;
            bh[nt][0] = Bh[(kb + c) * BSTRIDE + n];
            bh[nt][1] = Bh[(kb + c + 4) * BSTRIDE + n];
        }
#pragma unroll
        for (int mt = 0; mt < 4; mt++)
#pragma unroll
            for (int nt = 0; nt < 4; nt++)
                mma16816(d[mt][nt], ah[mt], bh[nt][0], bh[nt][1]);
    }
}

#define AWORDS (128 * ASTRIDE)   // 2560
#define BWORDS (16 * BSTRIDE)    // 2176

// ----------------------------- FFN1: H = gelu(X @ W1 + b1) -----------------
// grid (D_FF/128, 64, 9), 256 threads, BK=32, 2-stage double buffer.
__global__ void __launch_bounds__(256)
k_ffn1(const float* __restrict__ b1, const float* __restrict__ ub1) {
    const int z    = blockIdx.z;
    const int roff = g_offset[z];
    const int cnt  = g_offset[z + 1] - roff;
    const int m0   = blockIdx.y * 128;
    if (m0 >= cnt) return;
    const int f0   = blockIdx.x * 128;

    const uint32_t* __restrict__ Wp = g_W1p + (size_t)z * XKP * D_FF;
    const float* __restrict__ bias  = (z < N_EXPERTS) ? (b1 + (size_t)z * D_FF) : ub1;

    __shared__ int      s_tok[128];
    __shared__ uint32_t As_h[2][AWORDS];
    __shared__ uint32_t Bs_h[2][BWORDS];

    const int tid  = threadIdx.x;
    const int wid  = tid >> 5;
    const int lane = tid & 31;
    const int wm = wid >> 2, wn = wid & 3;
    const int g = lane >> 2, c = lane & 3;

    if (tid < 128) {
        const int mm = m0 + tid;
        s_tok[tid] = g_assign_tok[roff + ((mm < cnt) ? mm : 0)];
    }
    __syncthreads();

    // staging indices: A (row, kp): row = tid>>4 + 16q, kp = tid&15
    //                  B (kp, col): kp = tid>>7 + 2q,  col = tid&127
    const int rA0 = tid >> 4, kpA = tid & 15;
    const int kB0 = tid >> 7, fB  = tid & 127;
    unsigned arow[8];
#pragma unroll
    for (int q = 0; q < 8; q++)
        arow[q] = (unsigned)s_tok[rA0 + 16 * q] * (unsigned)XKP;

    float d[4][4][4];
#pragma unroll
    for (int a = 0; a < 4; a++)
#pragma unroll
        for (int b = 0; b < 4; b++)
#pragma unroll
            for (int e = 0; e < 4; e++) d[a][b][e] = 0.f;

    uint32_t pa[8], pb[8];
#pragma unroll
    for (int q = 0; q < 8; q++) {
        pa[q] = g_Xp[(size_t)arow[q] + kpA];
        pb[q] = Wp[(size_t)(kB0 + 2 * q) * D_FF + f0 + fB];
    }

    constexpr int NCH = D_MODEL / 32;   // 16 chunks of 16 k-pairs
    for (int ch = 0; ch < NCH; ch++) {
        const int buf = ch & 1;
#pragma unroll
        for (int q = 0; q < 8; q++) {
            As_h[buf][(rA0 + 16 * q) * ASTRIDE + kpA] = pa[q];
            Bs_h[buf][(kB0 + 2 * q) * BSTRIDE + fB]   = pb[q];
        }
        if (ch + 1 < NCH) {
            const int kp0 = (ch + 1) * 16;
#pragma unroll
            for (int q = 0; q < 8; q++) {
                pa[q] = g_Xp[(size_t)arow[q] + kp0 + kpA];
                pb[q] = Wp[(size_t)(kp0 + kB0 + 2 * q) * D_FF + f0 + fB];
            }
        }
        __syncthreads();
        mma_chunk32(d, As_h[buf], Bs_h[buf], wm, wn, g, c);
    }

    // epilogue: bias + exact gelu -> packed fp16 H
#pragma unroll
    for (int mt = 0; mt < 4; mt++)
#pragma unroll
        for (int half = 0; half < 2; half++) {
            const int m = wm * 64 + mt * 16 + g + half * 8;
            if (m0 + m >= cnt) continue;
            const size_t hbase = (size_t)(roff + m0 + m) * HKP;
#pragma unroll
            for (int nt = 0; nt < 4; nt++) {
                const int f = f0 + wn * 32 + nt * 8 + 2 * c;
                float v0 = d[mt][nt][half * 2 + 0] + bias[f];
                float v1 = d[mt][nt][half * 2 + 1] + bias[f + 1];
                v0 = 0.5f * v0 * (1.0f + erff(v0 * 0.70710678118654752f));
                v1 = 0.5f * v1 * (1.0f + erff(v1 * 0.70710678118654752f));
                g_Hh[hbase + (f >> 1)] = pack2h(v0, v1);
            }
        }
}

// ----------------------------- FFN2: out += w*(H @ W2 + b2) ----------------
// grid (D_MODEL/128, 64, 9), BK=32, 2-stage double buffer.
__global__ void __launch_bounds__(256)
k_ffn2(float* __restrict__ out,
       const float* __restrict__ b2, const float* __restrict__ ub2) {
    const int z    = blockIdx.z;
    const int roff = g_offset[z];
    const int cnt  = g_offset[z + 1] - roff;
    const int m0   = blockIdx.y * 128;
    if (m0 >= cnt) return;
    const int d0   = blockIdx.x * 128;

    const uint32_t* __restrict__ Wp = g_W2p + (size_t)z * HKP * D_MODEL;
    const float* __restrict__ bias  = (z < N_EXPERTS) ? (b2 + (size_t)z * D_MODEL) : ub2;

    __shared__ int      s_tok[128];
    __shared__ float    s_w[128];
    __shared__ uint32_t As_h[2][AWORDS];
    __shared__ uint32_t Bs_h[2][BWORDS];

    const int tid  = threadIdx.x;
    const int wid  = tid >> 5;
    const int lane = tid & 31;
    const int wm = wid >> 2, wn = wid & 3;
    const int g = lane >> 2, c = lane & 3;

    if (tid < 128) {
        const int mm = m0 + tid;
        const int rr = roff + ((mm < cnt) ? mm : 0);
        s_tok[tid] = g_assign_tok[rr];
        s_w[tid]   = g_assign_w[rr];
    }
    __syncthreads();

    const int rA0 = tid >> 4, kpA = tid & 15;
    const int kB0 = tid >> 7, fB  = tid & 127;
    unsigned arow[8];
#pragma unroll
    for (int q = 0; q < 8; q++) {
        const int mm = m0 + rA0 + 16 * q;
        arow[q] = (unsigned)(roff + ((mm < cnt) ? mm : m0)) * (unsigned)HKP;
    }

    float d[4][4][4];
#pragma unroll
    for (int a = 0; a < 4; a++)
#pragma unroll
        for (int b = 0; b < 4; b++)
#pragma unroll
            for (int e = 0; e < 4; e++) d[a][b][e] = 0.f;

    uint32_t pa[8], pb[8];
#pragma unroll
    for (int q = 0; q < 8; q++) {
        pa[q] = g_Hh[(size_t)arow[q] + kpA];
        pb[q] = Wp[(size_t)(kB0 + 2 * q) * D_MODEL + d0 + fB];
    }

    constexpr int NCH = D_FF / 32;   // 64 chunks of 16 k-pairs
    for (int ch = 0; ch < NCH; ch++) {
        const int buf = ch & 1;
#pragma unroll
        for (int q = 0; q < 8; q++) {
            As_h[buf][(rA0 + 16 * q) * ASTRIDE + kpA] = pa[q];
            Bs_h[buf][(kB0 + 2 * q) * BSTRIDE + fB]   = pb[q];
        }
        if (ch + 1 < NCH) {
            const int kp0 = (ch + 1) * 16;
#pragma unroll
            for (int q = 0; q < 8; q++) {
                pa[q] = g_Hh[(size_t)arow[q] + kp0 + kpA];
                pb[q] = Wp[(size_t)(kp0 + kB0 + 2 * q) * D_MODEL + d0 + fB];
            }
        }
        __syncthreads();
        mma_chunk32(d, As_h[buf], Bs_h[buf], wm, wn, g, c);
    }

    // epilogue: weighted atomic accumulation
#pragma unroll
    for (int mt = 0; mt < 4; mt++)
#pragma unroll
        for (int half = 0; half < 2; half++) {
            const int m = wm * 64 + mt * 16 + g + half * 8;
            if (m0 + m >= cnt) continue;
            const int   tok = s_tok[m];
            const float wr  = s_w[m];
            float* orow = out + (size_t)tok * D_MODEL;
#pragma unroll
            for (int nt = 0; nt < 4; nt++) {
                const int dd = d0 + wn * 32 + nt * 8 + 2 * c;
                atomicAdd(&orow[dd],     wr * (d[mt][nt][half * 2 + 0] + bias[dd]));
                atomicAdd(&orow[dd + 1], wr * (d[mt][nt][half * 2 + 1] + bias[dd + 1]));
            }
        }
}

// ----------------------------- launch --------------------------------------
extern "C" void kernel_launch(void* const* d_in, const int* in_sizes, int n_in,
                              void* d_out, int out_size) {
    const float* x        = (const float*)d_in[0];
    const int*   task_ids = (const int*)  d_in[1];
    const float* temb     = (const float*)d_in[2];
    const float* gw       = (const float*)d_in[3];
    const float* gb       = (const float*)d_in[4];
    const float* w1       = (const float*)d_in[5];
    const float* b1       = (const float*)d_in[6];
    const float* w2       = (const float*)d_in[7];
    const float* b2       = (const float*)d_in[8];
    const float* uw1      = (const float*)d_in[9];
    const float* ub1      = (const float*)d_in[10];
    const float* uw2      = (const float*)d_in[11];
    const float* ub2      = (const float*)d_in[12];

    float* out        = (float*)d_out;
    float* out_logits = out + OUT_ELEMS;

    k_prep<<<ZB + W1B + W2B, 256>>>((float4*)out, w1, uw1, w2, uw2);
    k_gate<<<TOK, 256>>>(x, task_ids, temb, gw, gb, out_logits);
    k_scan<<<1, 32>>>();
    k_place<<<TOK / 256, 256>>>();
    k_ffn1<<<dim3(D_FF / 128, TOK / 128, NGRP), 256>>>(b1, ub1);
    k_ffn2<<<dim3(D_MODEL / 128, TOK / 128, NGRP), 256>>>(out, b2, ub2);
}

// round 14
// speedup vs baseline: 1.3518x; 1.1680x over previous
#include <cuda_runtime.h>
#include <cuda_fp16.h>
#include <math.h>
#include <stdint.h>

// ---------------------------------------------------------------------------
// TaskAwareMoE round 14: BK=64 + cp.async double-buffered staging (70KB smem).
// Same fp16 mma.sync math, same k order -> output bit-identical to R9/11/12/13.
// ---------------------------------------------------------------------------

#define D_MODEL   512
#define D_FF      2048
#define N_EXPERTS 8
#define BATCH     8
#define SEQ       1024
#define TOK       (BATCH * SEQ)            // 8192
#define EXP_ROWS  (2 * TOK)                // 16384
#define TOT_ROWS  (EXP_ROWS + TOK)         // 24576
#define OUT_ELEMS (TOK * D_MODEL)          // 4,194,304
#define NGRP      (N_EXPERTS + 1)
#define XKP       (D_MODEL / 2)            // 256 k-pairs per X row
#define HKP       (D_FF / 2)               // 1024 k-pairs per H row

#define BKP     32                          // k-pairs per chunk (BK=64)
#define ASTRIDE 36                          // words per A row (32 + 4 pad)
#define BSTRIDE 136                         // words per B k-pair row (128 + 8)
#define AWORDS  (128 * ASTRIDE)             // 4608
#define BWORDS  (BKP * BSTRIDE)             // 4352
#define STAGE_W (AWORDS + BWORDS)           // 8960 words
#define SMEM_DYN (2 * STAGE_W * 4)          // 71680 bytes

// ----------------------------- static scratch ------------------------------
__device__ uint32_t g_Hh[(size_t)TOT_ROWS * HKP];          // packed fp16x2 H
__device__ uint32_t g_Xp[(size_t)TOK * XKP];               // packed fp16x2 X
__device__ uint32_t g_W1p[(size_t)NGRP * XKP * D_FF];      // [g][kp][f]
__device__ uint32_t g_W2p[(size_t)NGRP * HKP * D_MODEL];   // [g][kp][d]
__device__ int   g_count[N_EXPERTS + 1];
__device__ int   g_offset[N_EXPERTS + 2];
__device__ int   g_cursor[N_EXPERTS];
__device__ int   g_tok_e0[TOK];
__device__ int   g_tok_e1[TOK];
__device__ float g_tok_p0[TOK];
__device__ float g_tok_p1[TOK];
__device__ float g_tok_om[TOK];
__device__ int   g_assign_tok[TOT_ROWS];
__device__ float g_assign_w[TOT_ROWS];

// ----------------------------- helpers -------------------------------------
__device__ __forceinline__ void mma16816(float d[4], const uint32_t a[4],
                                         uint32_t b0, uint32_t b1) {
    asm volatile(
        "mma.sync.aligned.m16n8k16.row.col.f32.f16.f16.f32 "
        "{%0,%1,%2,%3}, {%4,%5,%6,%7}, {%8,%9}, {%0,%1,%2,%3};"
        : "+f"(d[0]), "+f"(d[1]), "+f"(d[2]), "+f"(d[3])
        : "r"(a[0]), "r"(a[1]), "r"(a[2]), "r"(a[3]), "r"(b0), "r"(b1));
}
__device__ __forceinline__ uint32_t pack2h(float x, float y) {
    __half2 h = __floats2half2_rn(x, y);
    return *(uint32_t*)&h;
}
__device__ __forceinline__ uint32_t smem_u32(const void* p) {
    uint32_t a;
    asm("{ .reg .u64 t; cvta.to.shared.u64 t, %1; cvt.u32.u64 %0, t; }" : "=r"(a) : "l"(p));
    return a;
}
__device__ __forceinline__ void cp16(uint32_t s, const void* g) {
    asm volatile("cp.async.cg.shared.global [%0], [%1], 16;" :: "r"(s), "l"(g) : "memory");
}
#define CP_COMMIT() asm volatile("cp.async.commit_group;" ::: "memory")
#define CP_WAIT0()  asm volatile("cp.async.wait_group 0;" ::: "memory")

// ----------------------------- prep: zero out + pack W1/W2 -----------------
#define ZB  (OUT_ELEMS / 4 / 256)               // 4096 blocks
#define W1B (NGRP * XKP * D_FF / 256)           // 18432 blocks
#define W2B (NGRP * HKP * D_MODEL / 256)        // 18432 blocks

__global__ void k_prep(float4* __restrict__ out4,
                       const float* __restrict__ w1, const float* __restrict__ uw1,
                       const float* __restrict__ w2, const float* __restrict__ uw2) {
    const int b   = blockIdx.x;
    const int tid = threadIdx.x;
    if (b < ZB) {
        out4[b * 256 + tid] = make_float4(0.f, 0.f, 0.f, 0.f);
        if (b == 0 && tid <= N_EXPERTS) g_count[tid] = 0;
    } else if (b < ZB + W1B) {
        const unsigned j  = (unsigned)(b - ZB) * 256u + tid;
        const unsigned e  = j / (unsigned)(XKP * D_FF);
        const unsigned r  = j % (unsigned)(XKP * D_FF);
        const unsigned kp = r / (unsigned)D_FF, n = r % (unsigned)D_FF;
        const float* src = (e < N_EXPERTS) ? (w1 + (size_t)e * D_MODEL * D_FF) : uw1;
        g_W1p[j] = pack2h(src[(size_t)(2 * kp) * D_FF + n],
                          src[(size_t)(2 * kp + 1) * D_FF + n]);
    } else {
        const unsigned j  = (unsigned)(b - ZB - W1B) * 256u + tid;
        const unsigned e  = j / (unsigned)(HKP * D_MODEL);
        const unsigned r  = j % (unsigned)(HKP * D_MODEL);
        const unsigned kp = r / (unsigned)D_MODEL, n = r % (unsigned)D_MODEL;
        const float* src = (e < N_EXPERTS) ? (w2 + (size_t)e * D_FF * D_MODEL) : uw2;
        g_W2p[j] = pack2h(src[(size_t)(2 * kp) * D_MODEL + n],
                          src[(size_t)(2 * kp + 1) * D_MODEL + n]);
    }
}

// ----------------------------- gating (+ X packing) ------------------------
__global__ void k_gate(const float* __restrict__ x,
                       const int*   __restrict__ task_ids,
                       const float* __restrict__ temb,
                       const float* __restrict__ gw,
                       const float* __restrict__ gb,
                       float* __restrict__ out_logits) {
    const int t   = blockIdx.x;
    const int tid = threadIdx.x;
    const int task = task_ids[t / SEQ];
    const float* xr = x    + (size_t)t    * D_MODEL;
    const float* tr = temb + (size_t)task * D_MODEL;

    {
        float2 xv = *(const float2*)(xr + 2 * tid);
        g_Xp[(size_t)t * XKP + tid] = pack2h(xv.x, xv.y);
    }

    float acc[N_EXPERTS];
#pragma unroll
    for (int e = 0; e < N_EXPERTS; e++) acc[e] = 0.f;
    for (int d = tid; d < 2 * D_MODEL; d += 256) {
        float v = (d < D_MODEL) ? xr[d] : tr[d - D_MODEL];
        const float* g = gw + (size_t)d * N_EXPERTS;
#pragma unroll
        for (int e = 0; e < N_EXPERTS; e++) acc[e] += v * g[e];
    }
#pragma unroll
    for (int e = 0; e < N_EXPERTS; e++)
#pragma unroll
        for (int off = 16; off > 0; off >>= 1)
            acc[e] += __shfl_down_sync(0xffffffffu, acc[e], off);

    __shared__ float s_acc[8][N_EXPERTS];
    const int warp = tid >> 5, lane = tid & 31;
    if (lane == 0)
#pragma unroll
        for (int e = 0; e < N_EXPERTS; e++) s_acc[warp][e] = acc[e];
    __syncthreads();

    if (tid == 0) {
        float lg[N_EXPERTS];
#pragma unroll
        for (int e = 0; e < N_EXPERTS; e++) {
            float s = gb[e];
#pragma unroll
            for (int w = 0; w < 8; w++) s += s_acc[w][e];
            lg[e] = s;
            out_logits[(size_t)t * N_EXPERTS + e] = s;
        }
        int e0 = 0; float v0 = lg[0];
#pragma unroll
        for (int e = 1; e < N_EXPERTS; e++) if (lg[e] > v0) { v0 = lg[e]; e0 = e; }
        int e1 = -1; float v1 = -1e30f;
#pragma unroll
        for (int e = 0; e < N_EXPERTS; e++)
            if (e != e0 && lg[e] > v1) { v1 = lg[e]; e1 = e; }
        float ex = expf(v1 - v0);
        float p0 = 1.f / (1.f + ex);
        g_tok_e0[t] = e0;  g_tok_e1[t] = e1;
        g_tok_p0[t] = p0;  g_tok_p1[t] = ex / (1.f + ex);
        g_tok_om[t] = 1.f - p0;
        atomicAdd(&g_count[e0], 1);
        atomicAdd(&g_count[e1], 1);
    }
}

__global__ void k_scan() {
    if (blockIdx.x == 0 && threadIdx.x == 0) {
        int o = 0;
        for (int e = 0; e < N_EXPERTS; e++) { g_offset[e] = o; g_cursor[e] = o; o += g_count[e]; }
        g_offset[N_EXPERTS]     = o;
        g_offset[N_EXPERTS + 1] = o + TOK;
    }
}

__global__ void k_place() {
    const int t = blockIdx.x * 256 + threadIdx.x;
    const int e0 = g_tok_e0[t], e1 = g_tok_e1[t];
    const int p0pos = atomicAdd(&g_cursor[e0], 1);
    g_assign_tok[p0pos] = t;  g_assign_w[p0pos] = g_tok_p0[t];
    const int p1pos = atomicAdd(&g_cursor[e1], 1);
    g_assign_tok[p1pos] = t;  g_assign_w[p1pos] = g_tok_p1[t];
    const int ub = g_offset[N_EXPERTS] + t;
    g_assign_tok[ub] = t;     g_assign_w[ub] = g_tok_om[t];
}

// ---------------------------------------------------------------------------
// MMA over one BK=64 chunk (four k16 slabs, ascending k -> bit-identical).
// 8 warps (2x4), warp tile 64x32; g = lane>>2, c = lane&3.
// ---------------------------------------------------------------------------
__device__ __forceinline__ void mma_chunk64(float d[4][4][4],
                                            const uint32_t* Ah, const uint32_t* Bh,
                                            int wm, int wn, int g, int c) {
#pragma unroll
    for (int ks = 0; ks < 4; ks++) {
        const int kb = ks * 8;
        uint32_t ah[4][4];
#pragma unroll
        for (int mt = 0; mt < 4; mt++) {
            const int r0 = (wm * 64 + mt * 16 + g) * ASTRIDE + kb;
            const int r1 = r0 + 8 * ASTRIDE;
            ah[mt][0] = Ah[r0 + c];
            ah[mt][1] = Ah[r1 + c];
            ah[mt][2] = Ah[r0 + c + 4];
            ah[mt][3] = Ah[r1 + c + 4];
        }
        uint32_t bh[4][2];
#pragma unroll
        for (int nt = 0; nt < 4; nt++) {
            const int n = wn * 32 + nt * 8 + g;
            bh[nt][0] = Bh[(kb + c) * BSTRIDE + n];
            bh[nt][1] = Bh[(kb + c + 4) * BSTRIDE + n];
        }
#pragma unroll
        for (int mt = 0; mt < 4; mt++)
#pragma unroll
            for (int nt = 0; nt < 4; nt++)
                mma16816(d[mt][nt], ah[mt], bh[nt][0], bh[nt][1]);
    }
}

// stage one BK=64 chunk via cp.async (4 A segs + 4 B segs per thread)
// A: id = tid+256q -> row = id>>3, seg = id&7 (16B = 4 words)
// B: id = tid+256q -> kprow = id>>5, nseg = id&31
__device__ __forceinline__ void stage64(uint32_t sa, uint32_t sb,
                                        const uint32_t* __restrict__ Asrc,
                                        const unsigned* arow,
                                        const uint32_t* __restrict__ Bsrc,
                                        int bstride, int kp0, int tid) {
#pragma unroll
    for (int q = 0; q < 4; q++) {
        const int id  = tid + q * 256;
        const int row = id >> 3, seg = id & 7;
        cp16(sa + (uint32_t)(row * ASTRIDE + seg * 4) * 4u,
             Asrc + (size_t)arow[q] + kp0 + seg * 4);
        const int kpr = id >> 5, nseg = id & 31;
        cp16(sb + (uint32_t)(kpr * BSTRIDE + nseg * 4) * 4u,
             Bsrc + (size_t)(kp0 + kpr) * bstride + nseg * 4);
    }
    CP_COMMIT();
}

// ----------------------------- FFN1: H = gelu(X @ W1 + b1) -----------------
// grid (D_FF/128, 64, 9), 256 threads, BK=64, cp.async double buffer.
__global__ void __launch_bounds__(256)
k_ffn1(const float* __restrict__ b1, const float* __restrict__ ub1) {
    const int z    = blockIdx.z;
    const int roff = g_offset[z];
    const int cnt  = g_offset[z + 1] - roff;
    const int m0   = blockIdx.y * 128;
    if (m0 >= cnt) return;
    const int f0   = blockIdx.x * 128;

    const uint32_t* __restrict__ Wp = g_W1p + (size_t)z * XKP * D_FF;
    const float* __restrict__ bias  = (z < N_EXPERTS) ? (b1 + (size_t)z * D_FF) : ub1;

    extern __shared__ uint32_t dsm[];
    const uint32_t sbase = smem_u32(dsm);
    __shared__ int s_tok[128];

    const int tid  = threadIdx.x;
    const int wid  = tid >> 5;
    const int lane = tid & 31;
    const int wm = wid >> 2, wn = wid & 3;
    const int g = lane >> 2, c = lane & 3;

    if (tid < 128) {
        const int mm = m0 + tid;
        s_tok[tid] = g_assign_tok[roff + ((mm < cnt) ? mm : 0)];
    }
    __syncthreads();

    unsigned arow[4];
#pragma unroll
    for (int q = 0; q < 4; q++)
        arow[q] = (unsigned)s_tok[(tid + q * 256) >> 3] * (unsigned)XKP;

    // W offset for this tile's B columns (cols f0..f0+127, 16B seg from id&31)
    const uint32_t* Bsrc = Wp + f0;

    float d[4][4][4];
#pragma unroll
    for (int a = 0; a < 4; a++)
#pragma unroll
        for (int b = 0; b < 4; b++)
#pragma unroll
            for (int e = 0; e < 4; e++) d[a][b][e] = 0.f;

    constexpr int NCH = D_MODEL / 64;   // 8 chunks
    // prologue: stage chunk 0 into buf 0
    stage64(sbase, sbase + AWORDS * 4, g_Xp, arow, Bsrc, D_FF, 0, tid);

    for (int ch = 0; ch < NCH; ch++) {
        const int buf = ch & 1;
        CP_WAIT0();
        __syncthreads();
        if (ch + 1 < NCH) {
            const uint32_t sb2 = sbase + (uint32_t)(buf ^ 1) * STAGE_W * 4u;
            stage64(sb2, sb2 + AWORDS * 4, g_Xp, arow, Bsrc, D_FF, (ch + 1) * BKP, tid);
        }
        const uint32_t sb = sbase + (uint32_t)buf * STAGE_W * 4u;
        mma_chunk64(d, dsm + buf * STAGE_W, dsm + buf * STAGE_W + AWORDS, wm, wn, g, c);
        (void)sb;
    }

    // epilogue: bias + exact gelu -> packed fp16 H
#pragma unroll
    for (int mt = 0; mt < 4; mt++)
#pragma unroll
        for (int half = 0; half < 2; half++) {
            const int m = wm * 64 + mt * 16 + g + half * 8;
            if (m0 + m >= cnt) continue;
            const size_t hbase = (size_t)(roff + m0 + m) * HKP;
#pragma unroll
            for (int nt = 0; nt < 4; nt++) {
                const int f = f0 + wn * 32 + nt * 8 + 2 * c;
                float v0 = d[mt][nt][half * 2 + 0] + bias[f];
                float v1 = d[mt][nt][half * 2 + 1] + bias[f + 1];
                v0 = 0.5f * v0 * (1.0f + erff(v0 * 0.70710678118654752f));
                v1 = 0.5f * v1 * (1.0f + erff(v1 * 0.70710678118654752f));
                g_Hh[hbase + (f >> 1)] = pack2h(v0, v1);
            }
        }
}

// ----------------------------- FFN2: out += w*(H @ W2 + b2) ----------------
// grid (D_MODEL/128, 64, 9), BK=64, cp.async double buffer.
__global__ void __launch_bounds__(256)
k_ffn2(float* __restrict__ out,
       const float* __restrict__ b2, const float* __restrict__ ub2) {
    const int z    = blockIdx.z;
    const int roff = g_offset[z];
    const int cnt  = g_offset[z + 1] - roff;
    const int m0   = blockIdx.y * 128;
    if (m0 >= cnt) return;
    const int d0   = blockIdx.x * 128;

    const uint32_t* __restrict__ Wp = g_W2p + (size_t)z * HKP * D_MODEL;
    const float* __restrict__ bias  = (z < N_EXPERTS) ? (b2 + (size_t)z * D_MODEL) : ub2;

    extern __shared__ uint32_t dsm[];
    const uint32_t sbase = smem_u32(dsm);
    __shared__ int   s_tok[128];
    __shared__ float s_w[128];

    const int tid  = threadIdx.x;
    const int wid  = tid >> 5;
    const int lane = tid & 31;
    const int wm = wid >> 2, wn = wid & 3;
    const int g = lane >> 2, c = lane & 3;

    if (tid < 128) {
        const int mm = m0 + tid;
        const int rr = roff + ((mm < cnt) ? mm : 0);
        s_tok[tid] = g_assign_tok[rr];
        s_w[tid]   = g_assign_w[rr];
    }
    __syncthreads();

    unsigned arow[4];
#pragma unroll
    for (int q = 0; q < 4; q++) {
        const int mm = m0 + ((tid + q * 256) >> 3);
        arow[q] = (unsigned)(roff + ((mm < cnt) ? mm : m0)) * (unsigned)HKP;
    }
    const uint32_t* Bsrc = Wp + d0;

    float d[4][4][4];
#pragma unroll
    for (int a = 0; a < 4; a++)
#pragma unroll
        for (int b = 0; b < 4; b++)
#pragma unroll
            for (int e = 0; e < 4; e++) d[a][b][e] = 0.f;

    constexpr int NCH = D_FF / 64;   // 32 chunks
    stage64(sbase, sbase + AWORDS * 4, g_Hh, arow, Bsrc, D_MODEL, 0, tid);

    for (int ch = 0; ch < NCH; ch++) {
        const int buf = ch & 1;
        CP_WAIT0();
        __syncthreads();
        if (ch + 1 < NCH) {
            const uint32_t sb2 = sbase + (uint32_t)(buf ^ 1) * STAGE_W * 4u;
            stage64(sb2, sb2 + AWORDS * 4, g_Hh, arow, Bsrc, D_MODEL, (ch + 1) * BKP, tid);
        }
        mma_chunk64(d, dsm + buf * STAGE_W, dsm + buf * STAGE_W + AWORDS, wm, wn, g, c);
    }

    // epilogue: weighted atomic accumulation
#pragma unroll
    for (int mt = 0; mt < 4; mt++)
#pragma unroll
        for (int half = 0; half < 2; half++) {
            const int m = wm * 64 + mt * 16 + g + half * 8;
            if (m0 + m >= cnt) continue;
            const int   tok = s_tok[m];
            const float wr  = s_w[m];
            float* orow = out + (size_t)tok * D_MODEL;
#pragma unroll
            for (int nt = 0; nt < 4; nt++) {
                const int dd = d0 + wn * 32 + nt * 8 + 2 * c;
                atomicAdd(&orow[dd],     wr * (d[mt][nt][half * 2 + 0] + bias[dd]));
                atomicAdd(&orow[dd + 1], wr * (d[mt][nt][half * 2 + 1] + bias[dd + 1]));
            }
        }
}

// ----------------------------- launch --------------------------------------
extern "C" void kernel_launch(void* const* d_in, const int* in_sizes, int n_in,
                              void* d_out, int out_size) {
    const float* x        = (const float*)d_in[0];
    const int*   task_ids = (const int*)  d_in[1];
    const float* temb     = (const float*)d_in[2];
    const float* gw       = (const float*)d_in[3];
    const float* gb       = (const float*)d_in[4];
    const float* w1       = (const float*)d_in[5];
    const float* b1       = (const float*)d_in[6];
    const float* w2       = (const float*)d_in[7];
    const float* b2       = (const float*)d_in[8];
    const float* uw1      = (const float*)d_in[9];
    const float* ub1      = (const float*)d_in[10];
    const float* uw2      = (const float*)d_in[11];
    const float* ub2      = (const float*)d_in[12];

    float* out        = (float*)d_out;
    float* out_logits = out + OUT_ELEMS;

    cudaFuncSetAttribute(k_ffn1, cudaFuncAttributeMaxDynamicSharedMemorySize, SMEM_DYN);
    cudaFuncSetAttribute(k_ffn2, cudaFuncAttributeMaxDynamicSharedMemorySize, SMEM_DYN);

    k_prep<<<ZB + W1B + W2B, 256>>>((float4*)out, w1, uw1, w2, uw2);
    k_gate<<<TOK, 256>>>(x, task_ids, temb, gw, gb, out_logits);
    k_scan<<<1, 32>>>();
    k_place<<<TOK / 256, 256>>>();
    k_ffn1<<<dim3(D_FF / 128, TOK / 128, NGRP), 256, SMEM_DYN>>>(b1, ub1);
    k_ffn2<<<dim3(D_MODEL / 128, TOK / 128, NGRP), 256, SMEM_DYN>>>(out, b2, ub2);
}

// round 15
// speedup vs baseline: 1.4211x; 1.0513x over previous
#include <cuda_runtime.h>
#include <cuda_fp16.h>
#include <math.h>
#include <stdint.h>

// ---------------------------------------------------------------------------
// TaskAwareMoE round 15: BK=64 cp.async pipeline + ldmatrix fragment loads
// (4x fewer smem-pipe ops). B weights stored [n][kp] so A and B tiles share
// one layout. Same k order -> output bit-identical to R9/11-14.
// ---------------------------------------------------------------------------

#define D_MODEL   512
#define D_FF      2048
#define N_EXPERTS 8
#define BATCH     8
#define SEQ       1024
#define TOK       (BATCH * SEQ)            // 8192
#define EXP_ROWS  (2 * TOK)                // 16384
#define TOT_ROWS  (EXP_ROWS + TOK)         // 24576
#define OUT_ELEMS (TOK * D_MODEL)          // 4,194,304
#define NGRP      (N_EXPERTS + 1)
#define XKP       (D_MODEL / 2)            // 256 k-pairs per X row
#define HKP       (D_FF / 2)               // 1024 k-pairs per H row

#define BKP     32                          // k-pairs per chunk (BK=64)
#define ASTRIDE 36                          // words per tile row (32 + 4 pad)
#define TWORDS  (128 * ASTRIDE)             // 4608 words per tile
#define STAGE_W (2 * TWORDS)                // A + B
#define SMEM_DYN (2 * STAGE_W * 4)          // 73728 bytes

// ----------------------------- static scratch ------------------------------
__device__ uint32_t g_Hh[(size_t)TOT_ROWS * HKP];          // packed fp16x2 H [row][kp]
__device__ uint32_t g_Xp[(size_t)TOK * XKP];               // packed fp16x2 X [row][kp]
__device__ uint32_t g_W1p[(size_t)NGRP * D_FF * XKP];      // [g][f][kp]
__device__ uint32_t g_W2p[(size_t)NGRP * D_MODEL * HKP];   // [g][d][kp]
__device__ int   g_count[N_EXPERTS + 1];
__device__ int   g_offset[N_EXPERTS + 2];
__device__ int   g_cursor[N_EXPERTS];
__device__ int   g_tok_e0[TOK];
__device__ int   g_tok_e1[TOK];
__device__ float g_tok_p0[TOK];
__device__ float g_tok_p1[TOK];
__device__ float g_tok_om[TOK];
__device__ int   g_assign_tok[TOT_ROWS];
__device__ float g_assign_w[TOT_ROWS];

// ----------------------------- helpers -------------------------------------
__device__ __forceinline__ void mma16816(float d[4], const uint32_t a[4],
                                         uint32_t b0, uint32_t b1) {
    asm volatile(
        "mma.sync.aligned.m16n8k16.row.col.f32.f16.f16.f32 "
        "{%0,%1,%2,%3}, {%4,%5,%6,%7}, {%8,%9}, {%0,%1,%2,%3};"
        : "+f"(d[0]), "+f"(d[1]), "+f"(d[2]), "+f"(d[3])
        : "r"(a[0]), "r"(a[1]), "r"(a[2]), "r"(a[3]), "r"(b0), "r"(b1));
}
__device__ __forceinline__ void ldmx4(uint32_t r[4], uint32_t addr) {
    asm volatile("ldmatrix.sync.aligned.m8n8.x4.shared.b16 {%0,%1,%2,%3}, [%4];"
                 : "=r"(r[0]), "=r"(r[1]), "=r"(r[2]), "=r"(r[3]) : "r"(addr));
}
__device__ __forceinline__ uint32_t pack2h(float x, float y) {
    __half2 h = __floats2half2_rn(x, y);
    return *(uint32_t*)&h;
}
__device__ __forceinline__ uint32_t smem_u32(const void* p) {
    uint32_t a;
    asm("{ .reg .u64 t; cvta.to.shared.u64 t, %1; cvt.u32.u64 %0, t; }" : "=r"(a) : "l"(p));
    return a;
}
__device__ __forceinline__ void cp16(uint32_t s, const void* g) {
    asm volatile("cp.async.cg.shared.global [%0], [%1], 16;" :: "r"(s), "l"(g) : "memory");
}
#define CP_COMMIT() asm volatile("cp.async.commit_group;" ::: "memory")
#define CP_WAIT0()  asm volatile("cp.async.wait_group 0;" ::: "memory")

// ----------------------------- prep ----------------------------------------
// blocks: [0,ZB) zero out; [ZB,ZB+WTB) W1 transpose-pack; [..,+WTB) W2.
#define ZB  (OUT_ELEMS / 4 / 256)               // 4096
#define TPE 1024                                 // 32x32 tiles per expert (both Ws)
#define WTB (NGRP * TPE)                         // 9216

__global__ void k_prep(float4* __restrict__ out4,
                       const float* __restrict__ w1, const float* __restrict__ uw1,
                       const float* __restrict__ w2, const float* __restrict__ uw2) {
    __shared__ float tile[32][33];
    const int b   = blockIdx.x;
    const int tid = threadIdx.x;
    if (b < ZB) {
        out4[b * 256 + tid] = make_float4(0.f, 0.f, 0.f, 0.f);
        if (b == 0 && tid <= N_EXPERTS) g_count[tid] = 0;
        return;
    }
    const float* w; const float* uw; uint32_t* dst; int K_, N_, r;
    if (b < ZB + WTB) { r = b - ZB;       w = w1; uw = uw1; dst = g_W1p; K_ = D_MODEL; N_ = D_FF; }
    else              { r = b - ZB - WTB; w = w2; uw = uw2; dst = g_W2p; K_ = D_FF;    N_ = D_MODEL; }
    const int e  = r / TPE;
    const int t2 = r % TPE;
    const int ntiles = N_ / 32;
    const int k0 = (t2 / ntiles) * 32, n0 = (t2 % ntiles) * 32;
    const float* src = (e < N_EXPERTS) ? (w + (size_t)e * K_ * N_) : uw;

    const int tx = tid & 31, ty = tid >> 5;
#pragma unroll
    for (int i = 0; i < 4; i++)
        tile[ty + 8 * i][tx] = src[(size_t)(k0 + ty + 8 * i) * N_ + n0 + tx];
    __syncthreads();

    uint32_t* dptr = dst + (size_t)e * N_ * (K_ / 2);
#pragma unroll
    for (int o = 0; o < 2; o++) {
        const int idx = tid * 2 + o;
        const int nf = idx >> 4, kp = idx & 15;
        dptr[(size_t)(n0 + nf) * (K_ / 2) + (k0 >> 1) + kp] =
            pack2h(tile[2 * kp][nf], tile[2 * kp + 1][nf]);
    }
}

// ----------------------------- gating (+ X packing) ------------------------
__global__ void k_gate(const float* __restrict__ x,
                       const int*   __restrict__ task_ids,
                       const float* __restrict__ temb,
                       const float* __restrict__ gw,
                       const float* __restrict__ gb,
                       float* __restrict__ out_logits) {
    const int t   = blockIdx.x;
    const int tid = threadIdx.x;
    const int task = task_ids[t / SEQ];
    const float* xr = x    + (size_t)t    * D_MODEL;
    const float* tr = temb + (size_t)task * D_MODEL;

    {
        float2 xv = *(const float2*)(xr + 2 * tid);
        g_Xp[(size_t)t * XKP + tid] = pack2h(xv.x, xv.y);
    }

    float acc[N_EXPERTS];
#pragma unroll
    for (int e = 0; e < N_EXPERTS; e++) acc[e] = 0.f;
    for (int d = tid; d < 2 * D_MODEL; d += 256) {
        float v = (d < D_MODEL) ? xr[d] : tr[d - D_MODEL];
        const float* g = gw + (size_t)d * N_EXPERTS;
#pragma unroll
        for (int e = 0; e < N_EXPERTS; e++) acc[e] += v * g[e];
    }
#pragma unroll
    for (int e = 0; e < N_EXPERTS; e++)
#pragma unroll
        for (int off = 16; off > 0; off >>= 1)
            acc[e] += __shfl_down_sync(0xffffffffu, acc[e], off);

    __shared__ float s_acc[8][N_EXPERTS];
    const int warp = tid >> 5, lane = tid & 31;
    if (lane == 0)
#pragma unroll
        for (int e = 0; e < N_EXPERTS; e++) s_acc[warp][e] = acc[e];
    __syncthreads();

    if (tid == 0) {
        float lg[N_EXPERTS];
#pragma unroll
        for (int e = 0; e < N_EXPERTS; e++) {
            float s = gb[e];
#pragma unroll
            for (int w = 0; w < 8; w++) s += s_acc[w][e];
            lg[e] = s;
            out_logits[(size_t)t * N_EXPERTS + e] = s;
        }
        int e0 = 0; float v0 = lg[0];
#pragma unroll
        for (int e = 1; e < N_EXPERTS; e++) if (lg[e] > v0) { v0 = lg[e]; e0 = e; }
        int e1 = -1; float v1 = -1e30f;
#pragma unroll
        for (int e = 0; e < N_EXPERTS; e++)
            if (e != e0 && lg[e] > v1) { v1 = lg[e]; e1 = e; }
        float ex = expf(v1 - v0);
        float p0 = 1.f / (1.f + ex);
        g_tok_e0[t] = e0;  g_tok_e1[t] = e1;
        g_tok_p0[t] = p0;  g_tok_p1[t] = ex / (1.f + ex);
        g_tok_om[t] = 1.f - p0;
        atomicAdd(&g_count[e0], 1);
        atomicAdd(&g_count[e1], 1);
    }
}

__global__ void k_scan() {
    if (blockIdx.x == 0 && threadIdx.x == 0) {
        int o = 0;
        for (int e = 0; e < N_EXPERTS; e++) { g_offset[e] = o; g_cursor[e] = o; o += g_count[e]; }
        g_offset[N_EXPERTS]     = o;
        g_offset[N_EXPERTS + 1] = o + TOK;
    }
}

__global__ void k_place() {
    const int t = blockIdx.x * 256 + threadIdx.x;
    const int e0 = g_tok_e0[t], e1 = g_tok_e1[t];
    const int p0pos = atomicAdd(&g_cursor[e0], 1);
    g_assign_tok[p0pos] = t;  g_assign_w[p0pos] = g_tok_p0[t];
    const int p1pos = atomicAdd(&g_cursor[e1], 1);
    g_assign_tok[p1pos] = t;  g_assign_w[p1pos] = g_tok_p1[t];
    const int ub = g_offset[N_EXPERTS] + t;
    g_assign_tok[ub] = t;     g_assign_w[ub] = g_tok_om[t];
}

// ---------------------------------------------------------------------------
// BK=64 chunk via ldmatrix. Both tiles: 128 rows x 32 k-pair words, ASTRIDE.
// ---------------------------------------------------------------------------
__device__ __forceinline__ void mma_chunk64(float d[4][4][4],
                                            uint32_t aBase, uint32_t bBase,
                                            int wm, int wn, int lane) {
    const int arow = (lane & 7) + 8 * ((lane >> 3) & 1);
    const int acol = 4 * (lane >> 4);
    const int brow = (lane & 7) + 8 * (lane >> 4);
    const int bcol = 4 * ((lane >> 3) & 1);
#pragma unroll
    for (int ks = 0; ks < 4; ks++) {
        const int kb = ks * 8;
        uint32_t a[4][4];
#pragma unroll
        for (int mt = 0; mt < 4; mt++)
            ldmx4(a[mt], aBase + (uint32_t)(((wm * 64 + mt * 16 + arow) * ASTRIDE) + kb + acol) * 4u);
        uint32_t bf[2][4];
#pragma unroll
        for (int j = 0; j < 2; j++)
            ldmx4(bf[j], bBase + (uint32_t)(((wn * 32 + j * 16 + brow) * ASTRIDE) + kb + bcol) * 4u);
#pragma unroll
        for (int mt = 0; mt < 4; mt++)
#pragma unroll
            for (int nt = 0; nt < 4; nt++)
                mma16816(d[mt][nt], a[mt], bf[nt >> 1][(nt & 1) * 2], bf[nt >> 1][(nt & 1) * 2 + 1]);
    }
}

// stage one BK=64 chunk (A gathered rows, B contiguous weight rows)
__device__ __forceinline__ void stage64(uint32_t sa, uint32_t sb,
                                        const uint32_t* __restrict__ Asrc,
                                        const unsigned* arow,
                                        const uint32_t* __restrict__ Bsrc,
                                        int bkp, int kp0, int tid) {
#pragma unroll
    for (int q = 0; q < 4; q++) {
        const int id  = tid + q * 256;
        const int row = id >> 3, seg = id & 7;
        const uint32_t off = (uint32_t)(row * ASTRIDE + seg * 4) * 4u;
        cp16(sa + off, Asrc + (size_t)arow[q] + kp0 + seg * 4);
        cp16(sb + off, Bsrc + (size_t)row * bkp + kp0 + seg * 4);
    }
    CP_COMMIT();
}

// ----------------------------- FFN1: H = gelu(X @ W1 + b1) -----------------
__global__ void __launch_bounds__(256)
k_ffn1(const float* __restrict__ b1, const float* __restrict__ ub1) {
    const int z    = blockIdx.z;
    const int roff = g_offset[z];
    const int cnt  = g_offset[z + 1] - roff;
    const int m0   = blockIdx.y * 128;
    if (m0 >= cnt) return;
    const int f0   = blockIdx.x * 128;

    const uint32_t* __restrict__ Bsrc = g_W1p + (size_t)(z * D_FF + f0) * XKP;
    const float* __restrict__ bias    = (z < N_EXPERTS) ? (b1 + (size_t)z * D_FF) : ub1;

    extern __shared__ uint32_t dsm[];
    const uint32_t sbase = smem_u32(dsm);
    __shared__ int s_tok[128];

    const int tid  = threadIdx.x;
    const int wid  = tid >> 5;
    const int lane = tid & 31;
    const int wm = wid >> 2, wn = wid & 3;
    const int g = lane >> 2, c = lane & 3;

    if (tid < 128) {
        const int mm = m0 + tid;
        s_tok[tid] = g_assign_tok[roff + ((mm < cnt) ? mm : 0)];
    }
    __syncthreads();

    unsigned arow[4];
#pragma unroll
    for (int q = 0; q < 4; q++)
        arow[q] = (unsigned)s_tok[(tid + q * 256) >> 3] * (unsigned)XKP;

    float d[4][4][4];
#pragma unroll
    for (int a = 0; a < 4; a++)
#pragma unroll
        for (int b = 0; b < 4; b++)
#pragma unroll
            for (int e = 0; e < 4; e++) d[a][b][e] = 0.f;

    constexpr int NCH = D_MODEL / 64;   // 8 chunks
    stage64(sbase, sbase + TWORDS * 4, g_Xp, arow, Bsrc, XKP, 0, tid);

    for (int ch = 0; ch < NCH; ch++) {
        const int buf = ch & 1;
        CP_WAIT0();
        __syncthreads();
        if (ch + 1 < NCH) {
            const uint32_t s2 = sbase + (uint32_t)(buf ^ 1) * STAGE_W * 4u;
            stage64(s2, s2 + TWORDS * 4, g_Xp, arow, Bsrc, XKP, (ch + 1) * BKP, tid);
        }
        const uint32_t sb = sbase + (uint32_t)buf * STAGE_W * 4u;
        mma_chunk64(d, sb, sb + TWORDS * 4, wm, wn, lane);
    }

    // epilogue: bias + exact gelu -> packed fp16 H
#pragma unroll
    for (int mt = 0; mt < 4; mt++)
#pragma unroll
        for (int half = 0; half < 2; half++) {
            const int m = wm * 64 + mt * 16 + g + half * 8;
            if (m0 + m >= cnt) continue;
            const size_t hbase = (size_t)(roff + m0 + m) * HKP;
#pragma unroll
            for (int nt = 0; nt < 4; nt++) {
                const int f = f0 + wn * 32 + nt * 8 + 2 * c;
                float v0 = d[mt][nt][half * 2 + 0] + bias[f];
                float v1 = d[mt][nt][half * 2 + 1] + bias[f + 1];
                v0 = 0.5f * v0 * (1.0f + erff(v0 * 0.70710678118654752f));
                v1 = 0.5f * v1 * (1.0f + erff(v1 * 0.70710678118654752f));
                g_Hh[hbase + (f >> 1)] = pack2h(v0, v1);
            }
        }
}

// ----------------------------- FFN2: out += w*(H @ W2 + b2) ----------------
__global__ void __launch_bounds__(256)
k_ffn2(float* __restrict__ out,
       const float* __restrict__ b2, const float* __restrict__ ub2) {
    const int z    = blockIdx.z;
    const int roff = g_offset[z];
    const int cnt  = g_offset[z + 1] - roff;
    const int m0   = blockIdx.y * 128;
    if (m0 >= cnt) return;
    const int d0   = blockIdx.x * 128;

    const uint32_t* __restrict__ Bsrc = g_W2p + (size_t)(z * D_MODEL + d0) * HKP;
    const float* __restrict__ bias    = (z < N_EXPERTS) ? (b2 + (size_t)z * D_MODEL) : ub2;

    extern __shared__ uint32_t dsm[];
    const uint32_t sbase = smem_u32(dsm);
    __shared__ int   s_tok[128];
    __shared__ float s_w[128];

    const int tid  = threadIdx.x;
    const int wid  = tid >> 5;
    const int lane = tid & 31;
    const int wm = wid >> 2, wn = wid & 3;
    const int g = lane >> 2, c = lane & 3;

    if (tid < 128) {
        const int mm = m0 + tid;
        const int rr = roff + ((mm < cnt) ? mm : 0);
        s_tok[tid] = g_assign_tok[rr];
        s_w[tid]   = g_assign_w[rr];
    }
    __syncthreads();

    unsigned arow[4];
#pragma unroll
    for (int q = 0; q < 4; q++) {
        const int mm = m0 + ((tid + q * 256) >> 3);
        arow[q] = (unsigned)(roff + ((mm < cnt) ? mm : m0)) * (unsigned)HKP;
    }

    float d[4][4][4];
#pragma unroll
    for (int a = 0; a < 4; a++)
#pragma unroll
        for (int b = 0; b < 4; b++)
#pragma unroll
            for (int e = 0; e < 4; e++) d[a][b][e] = 0.f;

    constexpr int NCH = D_FF / 64;   // 32 chunks
    stage64(sbase, sbase + TWORDS * 4, g_Hh, arow, Bsrc, HKP, 0, tid);

    for (int ch = 0; ch < NCH; ch++) {
        const int buf = ch & 1;
        CP_WAIT0();
        __syncthreads();
        if (ch + 1 < NCH) {
            const uint32_t s2 = sbase + (uint32_t)(buf ^ 1) * STAGE_W * 4u;
            stage64(s2, s2 + TWORDS * 4, g_Hh, arow, Bsrc, HKP, (ch + 1) * BKP, tid);
        }
        const uint32_t sb = sbase + (uint32_t)buf * STAGE_W * 4u;
        mma_chunk64(d, sb, sb + TWORDS * 4, wm, wn, lane);
    }

    // epilogue: weighted atomic accumulation
#pragma unroll
    for (int mt = 0; mt < 4; mt++)
#pragma unroll
        for (int half = 0; half < 2; half++) {
            const int m = wm * 64 + mt * 16 + g + half * 8;
            if (m0 + m >= cnt) continue;
            const int   tok = s_tok[m];
            const float wr  = s_w[m];
            float* orow = out + (size_t)tok * D_MODEL;
#pragma unroll
            for (int nt = 0; nt < 4; nt++) {
                const int dd = d0 + wn * 32 + nt * 8 + 2 * c;
                atomicAdd(&orow[dd],     wr * (d[mt][nt][half * 2 + 0] + bias[dd]));
                atomicAdd(&orow[dd + 1], wr * (d[mt][nt][half * 2 + 1] + bias[dd + 1]));
            }
        }
}

// ----------------------------- launch --------------------------------------
extern "C" void kernel_launch(void* const* d_in, const int* in_sizes, int n_in,
                              void* d_out, int out_size) {
    const float* x        = (const float*)d_in[0];
    const int*   task_ids = (const int*)  d_in[1];
    const float* temb     = (const float*)d_in[2];
    const float* gw       = (const float*)d_in[3];
    const float* gb       = (const float*)d_in[4];
    const float* w1       = (const float*)d_in[5];
    const float* b1       = (const float*)d_in[6];
    const float* w2       = (const float*)d_in[7];
    const float* b2       = (const float*)d_in[8];
    const float* uw1      = (const float*)d_in[9];
    const float* ub1      = (const float*)d_in[10];
    const float* uw2      = (const float*)d_in[11];
    const float* ub2      = (const float*)d_in[12];

    float* out        = (float*)d_out;
    float* out_logits = out + OUT_ELEMS;

    cudaFuncSetAttribute(k_ffn1, cudaFuncAttributeMaxDynamicSharedMemorySize, SMEM_DYN);
    cudaFuncSetAttribute(k_ffn2, cudaFuncAttributeMaxDynamicSharedMemorySize, SMEM_DYN);

    k_prep<<<ZB + 2 * WTB, 256>>>((float4*)out, w1, uw1, w2, uw2);
    k_gate<<<TOK, 256>>>(x, task_ids, temb, gw, gb, out_logits);
    k_scan<<<1, 32>>>();
    k_place<<<TOK / 256, 256>>>();
    k_ffn1<<<dim3(D_FF / 128, TOK / 128, NGRP), 256, SMEM_DYN>>>(b1, ub1);
    k_ffn2<<<dim3(D_MODEL / 128, TOK / 128, NGRP), 256, SMEM_DYN>>>(out, b2, ub2);
}